// round 2
// baseline (speedup 1.0000x reference)
#include <cuda_runtime.h>
#include <cstdint>

// LocalDotAttention: B=4, H=16, S=2048, DK=DV=64, fp32.
// out = (sum_k exp(s_k - m) * decay(i,k) * V_k) / (sum_k exp(s_k - m))
// masked keys (mask_out truthy) contribute exactly 0 (exp(-1e9-m) underflows) -> skip.
// mask is read as 32-bit words (bool is upcast host-side; !=0 covers int32 and fp32).

#define BATCH 4
#define HEADS 16
#define SEQ   2048
#define DIM   64
#define BM    128   // queries per block (1 per thread)
#define BN    64    // keys per tile

// ---- packed f32x2 helpers (Blackwell FFMA2 path, PTX-only) ----
__device__ __forceinline__ void ffma2(unsigned long long& d, unsigned long long a, unsigned long long b) {
    asm("fma.rn.f32x2 %0, %1, %2, %0;" : "+l"(d) : "l"(a), "l"(b));
}
__device__ __forceinline__ unsigned long long fmul2(unsigned long long a, unsigned long long b) {
    unsigned long long r;
    asm("mul.rn.f32x2 %0, %1, %2;" : "=l"(r) : "l"(a), "l"(b));
    return r;
}
__device__ __forceinline__ unsigned long long pack2(float lo, float hi) {
    unsigned long long r;
    asm("mov.b64 %0, {%1, %2};" : "=l"(r) : "f"(lo), "f"(hi));
    return r;
}
__device__ __forceinline__ float2 unpack2(unsigned long long v) {
    float lo, hi;
    asm("mov.b64 {%0, %1}, %2;" : "=f"(lo), "=f"(hi) : "l"(v));
    return make_float2(lo, hi);
}

__global__ __launch_bounds__(BM, 2)
void local_dot_attn_kernel(const float* __restrict__ Q,
                           const float* __restrict__ K,
                           const float* __restrict__ V,
                           const unsigned int* __restrict__ mask_out,  // 32-bit per element
                           float* __restrict__ O)
{
    __shared__ float Ksh[BN][DIM];
    __shared__ float Vsh[BN][DIM];
    __shared__ unsigned int msh[BN];

    const int tid = threadIdx.x;
    const int qt  = blockIdx.x;   // query tile
    const int h   = blockIdx.y;
    const int b   = blockIdx.z;
    const int i   = qt * BM + tid;        // this thread's query row
    const size_t bh = (size_t)b * HEADS + h;

    // Load this thread's Q row into packed f32x2 registers (32 x u64 = 64 floats)
    unsigned long long q2[DIM / 2];
    unsigned long long acc2[DIM / 2];
    {
        const ulonglong2* q16 = (const ulonglong2*)(Q + (bh * SEQ + (size_t)i) * DIM);
        #pragma unroll
        for (int t = 0; t < 16; t++) {
            ulonglong2 v = q16[t];
            q2[2 * t]     = v.x;
            q2[2 * t + 1] = v.y;
        }
    }
    #pragma unroll
    for (int t = 0; t < DIM / 2; t++) acc2[t] = 0ull;   // packed {0.f, 0.f}

    float m = -INFINITY;   // running max
    float l = 0.f;         // running denominator
    const float scale  = 0.125f;                            // 1/sqrt(64)
    const float cdecay = 2.0f / ((float)SEQ * (float)SEQ);  // decay coefficient
    const float fi = (float)i;

    const float* kb = K + bh * SEQ * DIM;
    const float* vb = V + bh * SEQ * DIM;
    const unsigned int* mb = mask_out + (size_t)b * SEQ;

    for (int kt = 0; kt < SEQ; kt += BN) {
        // ---- stage K/V tile + mask tile into SMEM (coalesced float4) ----
        {
            const float4* kg = (const float4*)(kb + (size_t)kt * DIM);
            const float4* vg = (const float4*)(vb + (size_t)kt * DIM);
            float4* ks4 = (float4*)&Ksh[0][0];
            float4* vs4 = (float4*)&Vsh[0][0];
            #pragma unroll
            for (int t = 0; t < (BN * DIM / 4) / BM; t++) {   // 1024/128 = 8 iters
                ks4[tid + t * BM] = kg[tid + t * BM];
                vs4[tid + t * BM] = vg[tid + t * BM];
            }
            if (tid < BN) msh[tid] = mb[kt + tid];
        }
        __syncthreads();

        #pragma unroll 1
        for (int j = 0; j < BN; j++) {
            if (msh[j] != 0u) continue;  // uniform across block: mask depends only on (b, key)

            // s = q . K[j]  (two packed chains to hide FMA latency)
            const ulonglong2* krow = (const ulonglong2*)&Ksh[j][0];
            unsigned long long sa = 0ull, sb = 0ull;
            #pragma unroll
            for (int t = 0; t < 16; t++) {
                ulonglong2 kk = krow[t];
                ffma2(sa, q2[2 * t],     kk.x);
                ffma2(sb, q2[2 * t + 1], kk.y);
            }
            float2 ua = unpack2(sa), ub = unpack2(sb);
            float s = ((ua.x + ua.y) + (ub.x + ub.y)) * scale;

            // online softmax update (rescale is a rare record event)
            float p;
            if (s > m) {
                float corr = __expf(m - s);    // first hit: exp(-inf) = 0
                l *= corr;
                unsigned long long c2 = pack2(corr, corr);
                #pragma unroll
                for (int t = 0; t < DIM / 2; t++) acc2[t] = fmul2(acc2[t], c2);
                m = s;
                p = 1.f;
            } else {
                p = __expf(s - m);
            }
            l += p;

            float rel = fi - (float)(kt + j);
            float pd  = p * __expf(-rel * rel * cdecay);
            unsigned long long pd2 = pack2(pd, pd);

            const ulonglong2* vrow = (const ulonglong2*)&Vsh[j][0];
            #pragma unroll
            for (int t = 0; t < 16; t++) {
                ulonglong2 vv = vrow[t];
                ffma2(acc2[2 * t],     pd2, vv.x);
                ffma2(acc2[2 * t + 1], pd2, vv.y);
            }
        }
        __syncthreads();
    }

    // out = acc / l
    float inv = (l > 0.f) ? (1.f / l) : 0.f;
    unsigned long long inv2 = pack2(inv, inv);
    ulonglong2* orow = (ulonglong2*)(O + (bh * SEQ + (size_t)i) * DIM);
    #pragma unroll
    for (int t = 0; t < 16; t++) {
        ulonglong2 w;
        w.x = fmul2(acc2[2 * t],     inv2);
        w.y = fmul2(acc2[2 * t + 1], inv2);
        orow[t] = w;
    }
}

extern "C" void kernel_launch(void* const* d_in, const int* in_sizes, int n_in,
                              void* d_out, int out_size)
{
    const float* Q = (const float*)d_in[0];
    const float* K = (const float*)d_in[1];
    const float* V = (const float*)d_in[2];
    const unsigned int* mask = (const unsigned int*)d_in[3];
    float* O = (float*)d_out;

    dim3 grid(SEQ / BM, HEADS, BATCH);   // (16, 16, 4)
    local_dot_attn_kernel<<<grid, BM>>>(Q, K, V, mask, O);
}

// round 8
// speedup vs baseline: 1.7876x; 1.7876x over previous
#include <cuda_runtime.h>
#include <cstdint>

// ===================== problem constants =====================
#define BATCH 4
#define HEADS 16
#define SEQ   2048
#define DIM   64
#define BH    (BATCH*HEADS)
#define TELEMS (BH*SEQ*DIM)      // 8,388,608
#define MQ    128                // queries per CTA
#define NKV   64                 // keys per tile
#define NTILES (SEQ/NKV)         // 32
#define RS    144                // SMEM row stride bytes (72 bf16, conflict-free ldmatrix)

// ===================== device scratch: bf16 hi/lo splits =====================
__device__ uint4 g_Qh4[TELEMS/8];
__device__ uint4 g_Ql4[TELEMS/8];
__device__ uint4 g_Kh4[TELEMS/8];
__device__ uint4 g_Kl4[TELEMS/8];
__device__ uint4 g_Vh4[TELEMS/8];
__device__ uint4 g_Vl4[TELEMS/8];

// ===================== helpers =====================
__device__ __forceinline__ uint32_t smem_u32(const void* p) {
    uint32_t a;
    asm("{ .reg .u64 t; cvta.to.shared.u64 t, %1; cvt.u32.u64 %0, t; }" : "=r"(a) : "l"(p));
    return a;
}
__device__ __forceinline__ uint32_t pack_bf16x2(float hi, float lo) {
    uint32_t r;
    asm("cvt.rn.bf16x2.f32 %0, %1, %2;" : "=r"(r) : "f"(hi), "f"(lo));
    return r;
}
__device__ __forceinline__ float ex2f(float x) {
    float r;
    asm("ex2.approx.ftz.f32 %0, %1;" : "=f"(r) : "f"(x));
    return r;
}
__device__ __forceinline__ void ldm4(uint32_t r[4], uint32_t addr) {
    asm volatile("ldmatrix.sync.aligned.m8n8.x4.shared.b16 {%0,%1,%2,%3}, [%4];"
        : "=r"(r[0]), "=r"(r[1]), "=r"(r[2]), "=r"(r[3]) : "r"(addr));
}
__device__ __forceinline__ void ldm4t(uint32_t r[4], uint32_t addr) {
    asm volatile("ldmatrix.sync.aligned.m8n8.x4.trans.shared.b16 {%0,%1,%2,%3}, [%4];"
        : "=r"(r[0]), "=r"(r[1]), "=r"(r[2]), "=r"(r[3]) : "r"(addr));
}
__device__ __forceinline__ void mma16816(float c[4], const uint32_t a[4],
                                         uint32_t b0, uint32_t b1) {
    asm volatile(
        "mma.sync.aligned.m16n8k16.row.col.f32.bf16.bf16.f32 "
        "{%0,%1,%2,%3}, {%4,%5,%6,%7}, {%8,%9}, {%0,%1,%2,%3};"
        : "+f"(c[0]), "+f"(c[1]), "+f"(c[2]), "+f"(c[3])
        : "r"(a[0]), "r"(a[1]), "r"(a[2]), "r"(a[3]), "r"(b0), "r"(b1));
}

// ===================== precompute: split Q(scaled)/K/V into bf16 hi/lo =====================
__global__ void convert_kernel(const float* __restrict__ Q,
                               const float* __restrict__ K,
                               const float* __restrict__ V) {
    size_t i4 = (size_t)blockIdx.x * 256 + threadIdx.x;   // over TELEMS/4 float4s

    float4 q = ((const float4*)Q)[i4];
    q.x *= 0.125f; q.y *= 0.125f; q.z *= 0.125f; q.w *= 0.125f;
    float4 k = ((const float4*)K)[i4];
    float4 v = ((const float4*)V)[i4];

    #define SPLIT4(src, dsth, dstl) do { \
        uint32_t h0 = pack_bf16x2(src.y, src.x), h1 = pack_bf16x2(src.w, src.z); \
        float r0 = src.x - __uint_as_float(h0 << 16); \
        float r1 = src.y - __uint_as_float(h0 & 0xFFFF0000u); \
        float r2 = src.z - __uint_as_float(h1 << 16); \
        float r3 = src.w - __uint_as_float(h1 & 0xFFFF0000u); \
        uint32_t l0 = pack_bf16x2(r1, r0), l1 = pack_bf16x2(r3, r2); \
        ((uint2*)dsth)[i4] = make_uint2(h0, h1); \
        ((uint2*)dstl)[i4] = make_uint2(l0, l1); \
    } while (0)

    SPLIT4(q, g_Qh4, g_Ql4);
    SPLIT4(k, g_Kh4, g_Kl4);
    SPLIT4(v, g_Vh4, g_Vl4);
    #undef SPLIT4
}

// ===================== attention kernel (mma.sync bf16) =====================
// SMEM: 4 tile buffers of 64 rows x 144B = 9216B each (KH,KL,VH,VL).
// Q staging reuses the whole 36864B region (QH rows 0..127 at 0, QL at 18432).

__global__ __launch_bounds__(256)
void attn_kernel(const unsigned int* __restrict__ mask, float* __restrict__ O)
{
    __shared__ __align__(16) char sm[4 * 64 * RS];
    const uint32_t sb  = smem_u32(sm);
    const uint32_t sQH = sb, sQL = sb + 18432;
    const uint32_t sKH = sb, sKL = sb + 9216, sVH = sb + 18432, sVL = sb + 27648;

    const int tid  = threadIdx.x;
    const int w    = tid >> 5;
    const int lane = tid & 31;
    const int qt = blockIdx.x, h = blockIdx.y, b = blockIdx.z;
    const int bh = b * HEADS + h;

    // ---- stage Q (hi/lo) ----
    {
        const uint4* srcH = g_Qh4 + ((size_t)(bh * SEQ + qt * MQ) * DIM >> 3);
        const uint4* srcL = g_Ql4 + ((size_t)(bh * SEQ + qt * MQ) * DIM >> 3);
        #pragma unroll
        for (int i = 0; i < 4; i++) {
            int idx = tid + i * 256;          // 0..1023 (128 rows x 8 chunks)
            int r = idx >> 3, o = idx & 7;
            *(uint4*)(sm + (sQH - sb) + r * RS + o * 16) = srcH[idx];
            *(uint4*)(sm + (sQL - sb) + r * RS + o * 16) = srcL[idx];
        }
    }
    __syncthreads();

    // ---- load Q fragments (A operands), 16 rows per warp ----
    const int qa_row  = (lane & 7) + ((lane & 8) ? 8 : 0);
    const int qa_colb = (lane & 16) ? 16 : 0;
    uint32_t qfh[4][4], qfl[4][4];
    {
        uint32_t baseH = sQH + (16 * w + qa_row) * RS + qa_colb;
        uint32_t baseL = sQL + (16 * w + qa_row) * RS + qa_colb;
        #pragma unroll
        for (int ks = 0; ks < 4; ks++) {
            ldm4(qfh[ks], baseH + 32 * ks);
            ldm4(qfl[ks], baseL + 32 * ks);
        }
    }
    __syncthreads();   // Q region about to be overwritten by K/V tiles

    // ---- per-thread state ----
    float oacc[8][4];
    #pragma unroll
    for (int nt = 0; nt < 8; nt++)
        #pragma unroll
        for (int e = 0; e < 4; e++) oacc[nt][e] = 0.f;
    float m0 = -1e30f, m1 = -1e30f, l0 = 0.f, l1 = 0.f;

    const int   q4   = lane >> 2;
    const int   col0 = 2 * (lane & 3);
    const int   r0g  = qt * MQ + w * 16 + q4;     // global query row (thread's row 0)
    const float L2E  = 1.4426950408889634f;
    const float C2   = 6.879347314016243e-7f;     // (2/2048^2) * log2(e)
    const unsigned int* mrow = mask + (size_t)b * SEQ;

    // B-fragment address patterns
    const int kb_row  = (lane & 7) + ((lane & 16) ? 8 : 0);
    const int kb_colb = (lane & 8) ? 16 : 0;
    const int vb_row  = (lane & 7) + ((lane & 8) ? 8 : 0);
    const int vb_colb = (lane & 16) ? 16 : 0;

    const size_t tile_g0 = (size_t)bh * SEQ * DIM >> 3;   // uint4 base of this head

    for (int t = 0; t < NTILES; t++) {
        const int kt = t * NKV;
        // ---- load K/V tiles (hi/lo): 512 uint4 per buffer ----
        {
            size_t gbase = tile_g0 + (size_t)kt * DIM / 8;
            #pragma unroll
            for (int i = 0; i < 2; i++) {
                int idx = tid + i * 256;          // 0..511
                int r = idx >> 3, o = idx & 7;
                uint32_t d = r * RS + o * 16;
                *(uint4*)(sm + (sKH - sb) + d) = g_Kh4[gbase + idx];
                *(uint4*)(sm + (sKL - sb) + d) = g_Kl4[gbase + idx];
                *(uint4*)(sm + (sVH - sb) + d) = g_Vh4[gbase + idx];
                *(uint4*)(sm + (sVL - sb) + d) = g_Vl4[gbase + idx];
            }
        }
        // mask bits for this tile
        unsigned int mw0 = mrow[kt + lane];
        unsigned int mw1 = mrow[kt + 32 + lane];
        unsigned int mb0 = __ballot_sync(0xffffffffu, mw0 != 0u);
        unsigned int mb1 = __ballot_sync(0xffffffffu, mw1 != 0u);
        unsigned long long mbits = (unsigned long long)mb0 | ((unsigned long long)mb1 << 32);
        __syncthreads();

        // ---- S = Q K^T (3-term compensated) ----
        float c[8][4];
        #pragma unroll
        for (int nt = 0; nt < 8; nt++)
            #pragma unroll
            for (int e = 0; e < 4; e++) c[nt][e] = 0.f;

        #pragma unroll
        for (int ks = 0; ks < 4; ks++) {
            uint32_t bb[8][2];
            #pragma unroll
            for (int g = 0; g < 4; g++) {
                uint32_t r4[4];
                ldm4(r4, sKH + (16 * g + kb_row) * RS + 32 * ks + kb_colb);
                bb[2*g][0] = r4[0]; bb[2*g][1] = r4[1];
                bb[2*g+1][0] = r4[2]; bb[2*g+1][1] = r4[3];
            }
            #pragma unroll
            for (int nt = 0; nt < 8; nt++) mma16816(c[nt], qfh[ks], bb[nt][0], bb[nt][1]);
            #pragma unroll
            for (int nt = 0; nt < 8; nt++) mma16816(c[nt], qfl[ks], bb[nt][0], bb[nt][1]);
            #pragma unroll
            for (int g = 0; g < 4; g++) {
                uint32_t r4[4];
                ldm4(r4, sKL + (16 * g + kb_row) * RS + 32 * ks + kb_colb);
                bb[2*g][0] = r4[0]; bb[2*g][1] = r4[1];
                bb[2*g+1][0] = r4[2]; bb[2*g+1][1] = r4[3];
            }
            #pragma unroll
            for (int nt = 0; nt < 8; nt++) mma16816(c[nt], qfh[ks], bb[nt][0], bb[nt][1]);
        }

        // ---- epilogue: mask, online softmax, decay; build P fragments ----
        float mx0 = -1e30f, mx1 = -1e30f;
        #pragma unroll
        for (int nt = 0; nt < 8; nt++) {
            int j0 = 8 * nt + col0;
            bool k0 = (mbits >> j0) & 1ull;
            bool k1 = (mbits >> (j0 + 1)) & 1ull;
            if (k0) { c[nt][0] = -1e30f; c[nt][2] = -1e30f; }
            if (k1) { c[nt][1] = -1e30f; c[nt][3] = -1e30f; }
            mx0 = fmaxf(mx0, fmaxf(c[nt][0], c[nt][1]));
            mx1 = fmaxf(mx1, fmaxf(c[nt][2], c[nt][3]));
        }
        mx0 = fmaxf(mx0, __shfl_xor_sync(0xffffffffu, mx0, 1));
        mx0 = fmaxf(mx0, __shfl_xor_sync(0xffffffffu, mx0, 2));
        mx1 = fmaxf(mx1, __shfl_xor_sync(0xffffffffu, mx1, 1));
        mx1 = fmaxf(mx1, __shfl_xor_sync(0xffffffffu, mx1, 2));

        float mn0 = fmaxf(m0, mx0), mn1 = fmaxf(m1, mx1);
        float corr0 = ex2f((m0 - mn0) * L2E);
        float corr1 = ex2f((m1 - mn1) * L2E);
        m0 = mn0; m1 = mn1;

        float relA = (float)(r0g - kt - col0);   // row0, b=0; b=1 -> relA-1; row1 -> +8/+7
        float ls0 = 0.f, ls1 = 0.f;
        uint32_t ph0[8], ph1[8], pl0[8], pl1[8];
        #pragma unroll
        for (int nt = 0; nt < 8; nt++) {
            float rA0 = relA,        rA1 = relA - 1.f;
            float rB0 = relA + 8.f,  rB1 = relA + 7.f;
            float t00 = (c[nt][0] - m0) * L2E;
            float t01 = (c[nt][1] - m0) * L2E;
            float t10 = (c[nt][2] - m1) * L2E;
            float t11 = (c[nt][3] - m1) * L2E;
            ls0 += ex2f(t00) + ex2f(t01);
            ls1 += ex2f(t10) + ex2f(t11);
            float pd00 = ex2f(fmaf(-C2 * rA0, rA0, t00));
            float pd01 = ex2f(fmaf(-C2 * rA1, rA1, t01));
            float pd10 = ex2f(fmaf(-C2 * rB0, rB0, t10));
            float pd11 = ex2f(fmaf(-C2 * rB1, rB1, t11));
            uint32_t h0 = pack_bf16x2(pd01, pd00);
            uint32_t h1 = pack_bf16x2(pd11, pd10);
            float e00 = pd00 - __uint_as_float(h0 << 16);
            float e01 = pd01 - __uint_as_float(h0 & 0xFFFF0000u);
            float e10 = pd10 - __uint_as_float(h1 << 16);
            float e11 = pd11 - __uint_as_float(h1 & 0xFFFF0000u);
            ph0[nt] = h0; ph1[nt] = h1;
            pl0[nt] = pack_bf16x2(e01, e00);
            pl1[nt] = pack_bf16x2(e11, e10);
            relA -= 8.f;
        }
        l0 = l0 * corr0 + ls0;
        l1 = l1 * corr1 + ls1;

        // rescale O accumulators
        #pragma unroll
        for (int nt = 0; nt < 8; nt++) {
            oacc[nt][0] *= corr0; oacc[nt][1] *= corr0;
            oacc[nt][2] *= corr1; oacc[nt][3] *= corr1;
        }

        // ---- O += P V (3-term compensated), P from registers ----
        #pragma unroll
        for (int ksv = 0; ksv < 4; ksv++) {
            uint32_t ah[4] = { ph0[2*ksv], ph1[2*ksv], ph0[2*ksv+1], ph1[2*ksv+1] };
            uint32_t al[4] = { pl0[2*ksv], pl1[2*ksv], pl0[2*ksv+1], pl1[2*ksv+1] };
            uint32_t bb[8][2];
            #pragma unroll
            for (int g = 0; g < 4; g++) {
                uint32_t r4[4];
                ldm4t(r4, sVH + (16 * ksv + vb_row) * RS + 32 * g + vb_colb);
                bb[2*g][0] = r4[0]; bb[2*g][1] = r4[1];
                bb[2*g+1][0] = r4[2]; bb[2*g+1][1] = r4[3];
            }
            #pragma unroll
            for (int nt = 0; nt < 8; nt++) mma16816(oacc[nt], ah, bb[nt][0], bb[nt][1]);
            #pragma unroll
            for (int nt = 0; nt < 8; nt++) mma16816(oacc[nt], al, bb[nt][0], bb[nt][1]);
            #pragma unroll
            for (int g = 0; g < 4; g++) {
                uint32_t r4[4];
                ldm4t(r4, sVL + (16 * ksv + vb_row) * RS + 32 * g + vb_colb);
                bb[2*g][0] = r4[0]; bb[2*g][1] = r4[1];
                bb[2*g+1][0] = r4[2]; bb[2*g+1][1] = r4[3];
            }
            #pragma unroll
            for (int nt = 0; nt < 8; nt++) mma16816(oacc[nt], ah, bb[nt][0], bb[nt][1]);
        }
        __syncthreads();
    }

    // ---- reduce denominator across the quad (each thread holds 16/64 keys of its row) ----
    l0 += __shfl_xor_sync(0xffffffffu, l0, 1);
    l0 += __shfl_xor_sync(0xffffffffu, l0, 2);
    l1 += __shfl_xor_sync(0xffffffffu, l1, 1);
    l1 += __shfl_xor_sync(0xffffffffu, l1, 2);

    // ---- write out ----
    float inv0 = (l0 > 0.f) ? (1.f / l0) : 0.f;
    float inv1 = (l1 > 0.f) ? (1.f / l1) : 0.f;
    float* o0 = O + ((size_t)bh * SEQ + r0g) * DIM;
    float* o1 = o0 + 8 * DIM;
    #pragma unroll
    for (int nt = 0; nt < 8; nt++) {
        int j = 8 * nt + col0;
        *(float2*)(o0 + j) = make_float2(oacc[nt][0] * inv0, oacc[nt][1] * inv0);
        *(float2*)(o1 + j) = make_float2(oacc[nt][2] * inv1, oacc[nt][3] * inv1);
    }
}

// ===================== host launch =====================
extern "C" void kernel_launch(void* const* d_in, const int* in_sizes, int n_in,
                              void* d_out, int out_size)
{
    const float* Q = (const float*)d_in[0];
    const float* K = (const float*)d_in[1];
    const float* V = (const float*)d_in[2];
    const unsigned int* mask = (const unsigned int*)d_in[3];
    float* O = (float*)d_out;

    convert_kernel<<<TELEMS / 4 / 256, 256>>>(Q, K, V);
    attn_kernel<<<dim3(SEQ / MQ, HEADS, BATCH), 256>>>(mask, O);
}

// round 9
// speedup vs baseline: 4.3541x; 2.4357x over previous
#include <cuda_runtime.h>
#include <cstdint>

// ===================== problem constants =====================
#define BATCH 4
#define HEADS 16
#define SEQ   2048
#define DIM   64
#define BH    (BATCH*HEADS)
#define TELEMS (BH*SEQ*DIM)      // 8,388,608
#define MQ    128                // queries per CTA
#define NKV   64                 // keys per tile
#define RS    144                // SMEM row stride bytes (72 bf16, conflict-free ldmatrix)

// ===================== device scratch =====================
__device__ uint4 g_Qh4[TELEMS/8];
__device__ uint4 g_Ql4[TELEMS/8];
__device__ uint4 g_Kh4[TELEMS/8];    // compacted key order
__device__ uint4 g_Kl4[TELEMS/8];
__device__ uint4 g_Vh4[TELEMS/8];
__device__ uint4 g_Vl4[TELEMS/8];
__device__ int   g_kcnt[BATCH];      // unmasked keys per batch
__device__ int   g_kidx[BATCH*SEQ];  // compacted -> original key index
__device__ float g_kidxf[BATCH*SEQ]; // same, as float (for decay)

// ===================== helpers =====================
__device__ __forceinline__ uint32_t smem_u32(const void* p) {
    uint32_t a;
    asm("{ .reg .u64 t; cvta.to.shared.u64 t, %1; cvt.u32.u64 %0, t; }" : "=r"(a) : "l"(p));
    return a;
}
__device__ __forceinline__ uint32_t pack_bf16x2(float hi, float lo) {
    uint32_t r;
    asm("cvt.rn.bf16x2.f32 %0, %1, %2;" : "=r"(r) : "f"(hi), "f"(lo));
    return r;
}
__device__ __forceinline__ float ex2f(float x) {
    float r;
    asm("ex2.approx.ftz.f32 %0, %1;" : "=f"(r) : "f"(x));
    return r;
}
__device__ __forceinline__ void ldm4(uint32_t r[4], uint32_t addr) {
    asm volatile("ldmatrix.sync.aligned.m8n8.x4.shared.b16 {%0,%1,%2,%3}, [%4];"
        : "=r"(r[0]), "=r"(r[1]), "=r"(r[2]), "=r"(r[3]) : "r"(addr));
}
__device__ __forceinline__ void ldm4t(uint32_t r[4], uint32_t addr) {
    asm volatile("ldmatrix.sync.aligned.m8n8.x4.trans.shared.b16 {%0,%1,%2,%3}, [%4];"
        : "=r"(r[0]), "=r"(r[1]), "=r"(r[2]), "=r"(r[3]) : "r"(addr));
}
__device__ __forceinline__ void mma16816(float c[4], const uint32_t a[4],
                                         uint32_t b0, uint32_t b1) {
    asm volatile(
        "mma.sync.aligned.m16n8k16.row.col.f32.bf16.bf16.f32 "
        "{%0,%1,%2,%3}, {%4,%5,%6,%7}, {%8,%9}, {%0,%1,%2,%3};"
        : "+f"(c[0]), "+f"(c[1]), "+f"(c[2]), "+f"(c[3])
        : "r"(a[0]), "r"(a[1]), "r"(a[2]), "r"(a[3]), "r"(b0), "r"(b1));
}
__device__ __forceinline__ void split4(float4 s, uint2& hi, uint2& lo) {
    uint32_t h0 = pack_bf16x2(s.y, s.x), h1 = pack_bf16x2(s.w, s.z);
    float r0 = s.x - __uint_as_float(h0 << 16);
    float r1 = s.y - __uint_as_float(h0 & 0xFFFF0000u);
    float r2 = s.z - __uint_as_float(h1 << 16);
    float r3 = s.w - __uint_as_float(h1 & 0xFFFF0000u);
    hi = make_uint2(h0, h1);
    lo = make_uint2(pack_bf16x2(r1, r0), pack_bf16x2(r3, r2));
}

// ===================== kernel 1: compact unmasked key indices (per batch) =====================
__global__ void mask_scan_kernel(const unsigned int* __restrict__ mask) {
    __shared__ int wsum[32];
    __shared__ int woff[32];
    const int b = blockIdx.x;
    const int t = threadIdx.x;            // 1024 threads, 2 keys each
    const int lane = t & 31, wid = t >> 5;
    const unsigned int* mb = mask + (size_t)b * SEQ;

    int j0 = 2 * t, j1 = 2 * t + 1;
    int p0 = (mb[j0] == 0u) ? 1 : 0;      // keep unmasked
    int p1 = (mb[j1] == 0u) ? 1 : 0;
    int local = p0 + p1;

    int incl = local;
    #pragma unroll
    for (int d = 1; d < 32; d <<= 1) {
        int v = __shfl_up_sync(0xffffffffu, incl, d);
        if (lane >= d) incl += v;
    }
    if (lane == 31) wsum[wid] = incl;
    __syncthreads();
    if (wid == 0) {
        int v = wsum[lane];
        int iv = v;
        #pragma unroll
        for (int d = 1; d < 32; d <<= 1) {
            int u = __shfl_up_sync(0xffffffffu, iv, d);
            if (lane >= d) iv += u;
        }
        woff[lane] = iv - v;
        if (lane == 31) g_kcnt[b] = iv;
    }
    __syncthreads();

    int base = woff[wid] + (incl - local);
    if (p0) { g_kidx[b*SEQ + base] = j0; g_kidxf[b*SEQ + base] = (float)j0; base++; }
    if (p1) { g_kidx[b*SEQ + base] = j1; g_kidxf[b*SEQ + base] = (float)j1; }

    int cnt = g_kcnt[b];
    for (int j = cnt + t; j < SEQ; j += 1024) {
        g_kidx[b*SEQ + j]  = 0;
        g_kidxf[b*SEQ + j] = 0.f;
    }
}

// ===================== kernel 2: split Q (pre-scaled) =====================
__global__ void convert_q_kernel(const float* __restrict__ Q) {
    size_t i4 = (size_t)blockIdx.x * 256 + threadIdx.x;
    float4 q = ((const float4*)Q)[i4];
    q.x *= 0.125f; q.y *= 0.125f; q.z *= 0.125f; q.w *= 0.125f;
    uint2 hi, lo;
    split4(q, hi, lo);
    ((uint2*)g_Qh4)[i4] = hi;
    ((uint2*)g_Ql4)[i4] = lo;
}

// ===================== kernel 3: gather + split K/V in compacted key order =====================
__global__ void gather_kv_kernel(const float* __restrict__ K, const float* __restrict__ V) {
    size_t gid = (size_t)blockIdx.x * 256 + threadIdx.x;   // over TELEMS/4 = 2^21 chunks
    int chunk = (int)(gid & 15);          // 16 float4 per row (DIM=64)
    int j     = (int)((gid >> 4) & (SEQ - 1));
    int bh    = (int)(gid >> 15);
    int b     = bh >> 4;
    int cnt   = g_kcnt[b];

    uint2 kh = make_uint2(0, 0), kl = kh, vh = kh, vl = kh;
    if (j < cnt) {
        int o = g_kidx[b*SEQ + j];
        size_t src = ((size_t)bh * SEQ + o) * 16 + chunk;
        split4(((const float4*)K)[src], kh, kl);
        split4(((const float4*)V)[src], vh, vl);
    }
    size_t dst = ((size_t)bh * SEQ + j) * 16 + chunk;
    ((uint2*)g_Kh4)[dst] = kh;
    ((uint2*)g_Kl4)[dst] = kl;
    ((uint2*)g_Vh4)[dst] = vh;
    ((uint2*)g_Vl4)[dst] = vl;
}

// ===================== attention kernel (mma.sync bf16, compacted keys) =====================
__global__ __launch_bounds__(256, 2)
void attn_kernel(float* __restrict__ O)
{
    __shared__ __align__(16) char sm[4 * 64 * RS];
    __shared__ float fkt[64];
    const uint32_t sb  = smem_u32(sm);
    const uint32_t sQH = sb, sQL = sb + 18432;
    const uint32_t sKH = sb, sKL = sb + 9216, sVH = sb + 18432, sVL = sb + 27648;

    const int tid  = threadIdx.x;
    const int w    = tid >> 5;
    const int lane = tid & 31;
    const int qt = blockIdx.x, h = blockIdx.y, b = blockIdx.z;
    const int bh = b * HEADS + h;

    const int cnt   = g_kcnt[b];
    const int ntile = (cnt + 63) >> 6;

    // ---- stage Q (hi/lo) ----
    {
        const uint4* srcH = g_Qh4 + ((size_t)(bh * SEQ + qt * MQ) * DIM >> 3);
        const uint4* srcL = g_Ql4 + ((size_t)(bh * SEQ + qt * MQ) * DIM >> 3);
        #pragma unroll
        for (int i = 0; i < 4; i++) {
            int idx = tid + i * 256;
            int r = idx >> 3, o = idx & 7;
            *(uint4*)(sm + (sQH - sb) + r * RS + o * 16) = srcH[idx];
            *(uint4*)(sm + (sQL - sb) + r * RS + o * 16) = srcL[idx];
        }
    }
    __syncthreads();

    // ---- load Q fragments (A operands), 16 rows per warp ----
    const int qa_row  = (lane & 7) + ((lane & 8) ? 8 : 0);
    const int qa_colb = (lane & 16) ? 16 : 0;
    uint32_t qfh[4][4], qfl[4][4];
    {
        uint32_t baseH = sQH + (16 * w + qa_row) * RS + qa_colb;
        uint32_t baseL = sQL + (16 * w + qa_row) * RS + qa_colb;
        #pragma unroll
        for (int ks = 0; ks < 4; ks++) {
            ldm4(qfh[ks], baseH + 32 * ks);
            ldm4(qfl[ks], baseL + 32 * ks);
        }
    }
    __syncthreads();

    // ---- per-thread state ----
    float oacc[8][4];
    #pragma unroll
    for (int nt = 0; nt < 8; nt++)
        #pragma unroll
        for (int e = 0; e < 4; e++) oacc[nt][e] = 0.f;
    float m0 = -1e30f, m1 = -1e30f, l0 = 0.f, l1 = 0.f;

    const int   q4   = lane >> 2;
    const int   col0 = 2 * (lane & 3);
    const int   r0g  = qt * MQ + w * 16 + q4;
    const float fi0  = (float)r0g;
    const float L2E  = 1.4426950408889634f;
    const float C2   = 6.879347314016243e-7f;     // (2/2048^2) * log2(e)

    const int kb_row  = (lane & 7) + ((lane & 16) ? 8 : 0);
    const int kb_colb = (lane & 8) ? 16 : 0;
    const int vb_row  = (lane & 7) + ((lane & 8) ? 8 : 0);
    const int vb_colb = (lane & 16) ? 16 : 0;

    const size_t tile_g0 = (size_t)bh * SEQ * DIM >> 3;

    for (int t = 0; t < ntile; t++) {
        const int kt = t * NKV;
        // ---- load compacted K/V tiles (hi/lo) + original-index floats ----
        {
            size_t gbase = tile_g0 + (size_t)kt * DIM / 8;
            #pragma unroll
            for (int i = 0; i < 2; i++) {
                int idx = tid + i * 256;
                int r = idx >> 3, o = idx & 7;
                uint32_t d = r * RS + o * 16;
                *(uint4*)(sm + (sKH - sb) + d) = g_Kh4[gbase + idx];
                *(uint4*)(sm + (sKL - sb) + d) = g_Kl4[gbase + idx];
                *(uint4*)(sm + (sVH - sb) + d) = g_Vh4[gbase + idx];
                *(uint4*)(sm + (sVL - sb) + d) = g_Vl4[gbase + idx];
            }
            if (tid < 64) fkt[tid] = g_kidxf[b*SEQ + kt + tid];
        }
        __syncthreads();

        // ---- S = Q K^T (3-term compensated) ----
        float c[8][4];
        #pragma unroll
        for (int nt = 0; nt < 8; nt++)
            #pragma unroll
            for (int e = 0; e < 4; e++) c[nt][e] = 0.f;

        #pragma unroll
        for (int ks = 0; ks < 4; ks++) {
            uint32_t bb[8][2];
            #pragma unroll
            for (int g = 0; g < 4; g++) {
                uint32_t r4[4];
                ldm4(r4, sKH + (16 * g + kb_row) * RS + 32 * ks + kb_colb);
                bb[2*g][0] = r4[0]; bb[2*g][1] = r4[1];
                bb[2*g+1][0] = r4[2]; bb[2*g+1][1] = r4[3];
            }
            #pragma unroll
            for (int nt = 0; nt < 8; nt++) mma16816(c[nt], qfh[ks], bb[nt][0], bb[nt][1]);
            #pragma unroll
            for (int nt = 0; nt < 8; nt++) mma16816(c[nt], qfl[ks], bb[nt][0], bb[nt][1]);
            #pragma unroll
            for (int g = 0; g < 4; g++) {
                uint32_t r4[4];
                ldm4(r4, sKL + (16 * g + kb_row) * RS + 32 * ks + kb_colb);
                bb[2*g][0] = r4[0]; bb[2*g][1] = r4[1];
                bb[2*g+1][0] = r4[2]; bb[2*g+1][1] = r4[3];
            }
            #pragma unroll
            for (int nt = 0; nt < 8; nt++) mma16816(c[nt], qfh[ks], bb[nt][0], bb[nt][1]);
        }

        // ---- epilogue: tail mask, online softmax, decay; build P fragments ----
        const int lim = cnt - kt;       // >= 1; >= 64 except tail tile
        float mx0 = -1e30f, mx1 = -1e30f;
        #pragma unroll
        for (int nt = 0; nt < 8; nt++) {
            int j0 = 8 * nt + col0;
            if (j0 >= lim)     { c[nt][0] = -1e30f; c[nt][2] = -1e30f; }
            if (j0 + 1 >= lim) { c[nt][1] = -1e30f; c[nt][3] = -1e30f; }
            mx0 = fmaxf(mx0, fmaxf(c[nt][0], c[nt][1]));
            mx1 = fmaxf(mx1, fmaxf(c[nt][2], c[nt][3]));
        }
        mx0 = fmaxf(mx0, __shfl_xor_sync(0xffffffffu, mx0, 1));
        mx0 = fmaxf(mx0, __shfl_xor_sync(0xffffffffu, mx0, 2));
        mx1 = fmaxf(mx1, __shfl_xor_sync(0xffffffffu, mx1, 1));
        mx1 = fmaxf(mx1, __shfl_xor_sync(0xffffffffu, mx1, 2));

        float mn0 = fmaxf(m0, mx0), mn1 = fmaxf(m1, mx1);
        float corr0 = ex2f((m0 - mn0) * L2E);
        float corr1 = ex2f((m1 - mn1) * L2E);
        m0 = mn0; m1 = mn1;

        float ls0 = 0.f, ls1 = 0.f;
        uint32_t ph0[8], ph1[8], pl0[8], pl1[8];
        #pragma unroll
        for (int nt = 0; nt < 8; nt++) {
            float2 fk2 = *(float2*)&fkt[8 * nt + col0];
            float rA0 = fi0 - fk2.x, rA1 = fi0 - fk2.y;
            float rB0 = rA0 + 8.f,   rB1 = rA1 + 8.f;
            float t00 = (c[nt][0] - m0) * L2E;
            float t01 = (c[nt][1] - m0) * L2E;
            float t10 = (c[nt][2] - m1) * L2E;
            float t11 = (c[nt][3] - m1) * L2E;
            ls0 += ex2f(t00) + ex2f(t01);
            ls1 += ex2f(t10) + ex2f(t11);
            float pd00 = ex2f(fmaf(-C2 * rA0, rA0, t00));
            float pd01 = ex2f(fmaf(-C2 * rA1, rA1, t01));
            float pd10 = ex2f(fmaf(-C2 * rB0, rB0, t10));
            float pd11 = ex2f(fmaf(-C2 * rB1, rB1, t11));
            uint32_t h0 = pack_bf16x2(pd01, pd00);
            uint32_t h1 = pack_bf16x2(pd11, pd10);
            float e00 = pd00 - __uint_as_float(h0 << 16);
            float e01 = pd01 - __uint_as_float(h0 & 0xFFFF0000u);
            float e10 = pd10 - __uint_as_float(h1 << 16);
            float e11 = pd11 - __uint_as_float(h1 & 0xFFFF0000u);
            ph0[nt] = h0; ph1[nt] = h1;
            pl0[nt] = pack_bf16x2(e01, e00);
            pl1[nt] = pack_bf16x2(e11, e10);
        }
        l0 = l0 * corr0 + ls0;
        l1 = l1 * corr1 + ls1;

        #pragma unroll
        for (int nt = 0; nt < 8; nt++) {
            oacc[nt][0] *= corr0; oacc[nt][1] *= corr0;
            oacc[nt][2] *= corr1; oacc[nt][3] *= corr1;
        }

        // ---- O += P V (3-term compensated), P from registers ----
        #pragma unroll
        for (int ksv = 0; ksv < 4; ksv++) {
            uint32_t ah[4] = { ph0[2*ksv], ph1[2*ksv], ph0[2*ksv+1], ph1[2*ksv+1] };
            uint32_t al[4] = { pl0[2*ksv], pl1[2*ksv], pl0[2*ksv+1], pl1[2*ksv+1] };
            uint32_t bb[8][2];
            #pragma unroll
            for (int g = 0; g < 4; g++) {
                uint32_t r4[4];
                ldm4t(r4, sVH + (16 * ksv + vb_row) * RS + 32 * g + vb_colb);
                bb[2*g][0] = r4[0]; bb[2*g][1] = r4[1];
                bb[2*g+1][0] = r4[2]; bb[2*g+1][1] = r4[3];
            }
            #pragma unroll
            for (int nt = 0; nt < 8; nt++) mma16816(oacc[nt], ah, bb[nt][0], bb[nt][1]);
            #pragma unroll
            for (int nt = 0; nt < 8; nt++) mma16816(oacc[nt], al, bb[nt][0], bb[nt][1]);
            #pragma unroll
            for (int g = 0; g < 4; g++) {
                uint32_t r4[4];
                ldm4t(r4, sVL + (16 * ksv + vb_row) * RS + 32 * g + vb_colb);
                bb[2*g][0] = r4[0]; bb[2*g][1] = r4[1];
                bb[2*g+1][0] = r4[2]; bb[2*g+1][1] = r4[3];
            }
            #pragma unroll
            for (int nt = 0; nt < 8; nt++) mma16816(oacc[nt], ah, bb[nt][0], bb[nt][1]);
        }
        __syncthreads();
    }

    // ---- reduce denominator across the quad ----
    l0 += __shfl_xor_sync(0xffffffffu, l0, 1);
    l0 += __shfl_xor_sync(0xffffffffu, l0, 2);
    l1 += __shfl_xor_sync(0xffffffffu, l1, 1);
    l1 += __shfl_xor_sync(0xffffffffu, l1, 2);

    // ---- write out ----
    float inv0 = (l0 > 0.f) ? (1.f / l0) : 0.f;
    float inv1 = (l1 > 0.f) ? (1.f / l1) : 0.f;
    float* o0 = O + ((size_t)bh * SEQ + r0g) * DIM;
    float* o1 = o0 + 8 * DIM;
    #pragma unroll
    for (int nt = 0; nt < 8; nt++) {
        int j = 8 * nt + col0;
        *(float2*)(o0 + j) = make_float2(oacc[nt][0] * inv0, oacc[nt][1] * inv0);
        *(float2*)(o1 + j) = make_float2(oacc[nt][2] * inv1, oacc[nt][3] * inv1);
    }
}

// ===================== host launch =====================
extern "C" void kernel_launch(void* const* d_in, const int* in_sizes, int n_in,
                              void* d_out, int out_size)
{
    const float* Q = (const float*)d_in[0];
    const float* K = (const float*)d_in[1];
    const float* V = (const float*)d_in[2];
    const unsigned int* mask = (const unsigned int*)d_in[3];
    float* O = (float*)d_out;

    mask_scan_kernel<<<BATCH, 1024>>>(mask);
    convert_q_kernel<<<TELEMS / 4 / 256, 256>>>(Q);
    gather_kv_kernel<<<TELEMS / 4 / 256, 256>>>(K, V);
    attn_kernel<<<dim3(SEQ / MQ, HEADS, BATCH), 256>>>(O);
}

// round 10
// speedup vs baseline: 4.4011x; 1.0108x over previous
#include <cuda_runtime.h>
#include <cstdint>

// ===================== problem constants =====================
#define BATCH 4
#define HEADS 16
#define SEQ   2048
#define DIM   64
#define BH    (BATCH*HEADS)
#define TELEMS (BH*SEQ*DIM)      // 8,388,608
#define MQ    128                // queries per CTA
#define NKV   64                 // keys per tile
#define RS    144                // SMEM row stride bytes (72 bf16, conflict-free ldmatrix)

#define BUF_BYTES 36864          // 4 tiles x 64 rows x 144B
#define FKT_OFF   (2*BUF_BYTES)  // 73728
#define DSMEM_BYTES (2*BUF_BYTES + 2*256)   // 74240

// ===================== device scratch =====================
__device__ uint4 g_Qh4[TELEMS/8];
__device__ uint4 g_Ql4[TELEMS/8];
__device__ uint4 g_Kh4[TELEMS/8];    // compacted key order
__device__ uint4 g_Kl4[TELEMS/8];
__device__ uint4 g_Vh4[TELEMS/8];
__device__ uint4 g_Vl4[TELEMS/8];
__device__ int   g_kcnt[BATCH];      // unmasked keys per batch
__device__ int   g_kidx[BATCH*SEQ];  // compacted -> original key index
__device__ float g_kidxf[BATCH*SEQ]; // same, as float (for decay)

// ===================== helpers =====================
__device__ __forceinline__ uint32_t smem_u32(const void* p) {
    uint32_t a;
    asm("{ .reg .u64 t; cvta.to.shared.u64 t, %1; cvt.u32.u64 %0, t; }" : "=r"(a) : "l"(p));
    return a;
}
__device__ __forceinline__ uint32_t pack_bf16x2(float hi, float lo) {
    uint32_t r;
    asm("cvt.rn.bf16x2.f32 %0, %1, %2;" : "=r"(r) : "f"(hi), "f"(lo));
    return r;
}
__device__ __forceinline__ float ex2f(float x) {
    float r;
    asm("ex2.approx.ftz.f32 %0, %1;" : "=f"(r) : "f"(x));
    return r;
}
__device__ __forceinline__ void ldm4(uint32_t r[4], uint32_t addr) {
    asm volatile("ldmatrix.sync.aligned.m8n8.x4.shared.b16 {%0,%1,%2,%3}, [%4];"
        : "=r"(r[0]), "=r"(r[1]), "=r"(r[2]), "=r"(r[3]) : "r"(addr));
}
__device__ __forceinline__ void ldm4t(uint32_t r[4], uint32_t addr) {
    asm volatile("ldmatrix.sync.aligned.m8n8.x4.trans.shared.b16 {%0,%1,%2,%3}, [%4];"
        : "=r"(r[0]), "=r"(r[1]), "=r"(r[2]), "=r"(r[3]) : "r"(addr));
}
__device__ __forceinline__ void mma16816(float c[4], const uint32_t a[4],
                                         uint32_t b0, uint32_t b1) {
    asm volatile(
        "mma.sync.aligned.m16n8k16.row.col.f32.bf16.bf16.f32 "
        "{%0,%1,%2,%3}, {%4,%5,%6,%7}, {%8,%9}, {%0,%1,%2,%3};"
        : "+f"(c[0]), "+f"(c[1]), "+f"(c[2]), "+f"(c[3])
        : "r"(a[0]), "r"(a[1]), "r"(a[2]), "r"(a[3]), "r"(b0), "r"(b1));
}
__device__ __forceinline__ void split4(float4 s, uint2& hi, uint2& lo) {
    uint32_t h0 = pack_bf16x2(s.y, s.x), h1 = pack_bf16x2(s.w, s.z);
    float r0 = s.x - __uint_as_float(h0 << 16);
    float r1 = s.y - __uint_as_float(h0 & 0xFFFF0000u);
    float r2 = s.z - __uint_as_float(h1 << 16);
    float r3 = s.w - __uint_as_float(h1 & 0xFFFF0000u);
    hi = make_uint2(h0, h1);
    lo = make_uint2(pack_bf16x2(r1, r0), pack_bf16x2(r3, r2));
}
__device__ __forceinline__ void cpa16(uint32_t saddr, const void* gaddr) {
    asm volatile("cp.async.cg.shared.global [%0], [%1], 16;" :: "r"(saddr), "l"(gaddr));
}
#define CP_COMMIT() asm volatile("cp.async.commit_group;" ::: "memory")
#define CP_WAIT(n)  asm volatile("cp.async.wait_group %0;" :: "n"(n) : "memory")

// ===================== kernel 1: compact unmasked key indices (per batch) =====================
__global__ void mask_scan_kernel(const unsigned int* __restrict__ mask) {
    __shared__ int wsum[32];
    __shared__ int woff[32];
    const int b = blockIdx.x;
    const int t = threadIdx.x;            // 1024 threads, 2 keys each
    const int lane = t & 31, wid = t >> 5;
    const unsigned int* mb = mask + (size_t)b * SEQ;

    int j0 = 2 * t, j1 = 2 * t + 1;
    int p0 = (mb[j0] == 0u) ? 1 : 0;      // keep unmasked
    int p1 = (mb[j1] == 0u) ? 1 : 0;
    int local = p0 + p1;

    int incl = local;
    #pragma unroll
    for (int d = 1; d < 32; d <<= 1) {
        int v = __shfl_up_sync(0xffffffffu, incl, d);
        if (lane >= d) incl += v;
    }
    if (lane == 31) wsum[wid] = incl;
    __syncthreads();
    if (wid == 0) {
        int v = wsum[lane];
        int iv = v;
        #pragma unroll
        for (int d = 1; d < 32; d <<= 1) {
            int u = __shfl_up_sync(0xffffffffu, iv, d);
            if (lane >= d) iv += u;
        }
        woff[lane] = iv - v;
        if (lane == 31) g_kcnt[b] = iv;
    }
    __syncthreads();

    int base = woff[wid] + (incl - local);
    if (p0) { g_kidx[b*SEQ + base] = j0; g_kidxf[b*SEQ + base] = (float)j0; base++; }
    if (p1) { g_kidx[b*SEQ + base] = j1; g_kidxf[b*SEQ + base] = (float)j1; }

    int cnt = g_kcnt[b];
    for (int j = cnt + t; j < SEQ; j += 1024) {
        g_kidx[b*SEQ + j]  = 0;
        g_kidxf[b*SEQ + j] = 0.f;
    }
}

// ===================== kernel 2: split Q (pre-scaled) =====================
__global__ void convert_q_kernel(const float* __restrict__ Q) {
    size_t i4 = (size_t)blockIdx.x * 256 + threadIdx.x;
    float4 q = ((const float4*)Q)[i4];
    q.x *= 0.125f; q.y *= 0.125f; q.z *= 0.125f; q.w *= 0.125f;
    uint2 hi, lo;
    split4(q, hi, lo);
    ((uint2*)g_Qh4)[i4] = hi;
    ((uint2*)g_Ql4)[i4] = lo;
}

// ===================== kernel 3: gather + split K/V in compacted key order =====================
__global__ void gather_kv_kernel(const float* __restrict__ K, const float* __restrict__ V) {
    size_t gid = (size_t)blockIdx.x * 256 + threadIdx.x;   // over TELEMS/4 = 2^21 chunks
    int chunk = (int)(gid & 15);          // 16 float4 per row (DIM=64)
    int j     = (int)((gid >> 4) & (SEQ - 1));
    int bh    = (int)(gid >> 15);
    int b     = bh >> 4;
    int cnt   = g_kcnt[b];

    uint2 kh = make_uint2(0, 0), kl = kh, vh = kh, vl = kh;
    if (j < cnt) {
        int o = g_kidx[b*SEQ + j];
        size_t src = ((size_t)bh * SEQ + o) * 16 + chunk;
        split4(((const float4*)K)[src], kh, kl);
        split4(((const float4*)V)[src], vh, vl);
    }
    size_t dst = ((size_t)bh * SEQ + j) * 16 + chunk;
    ((uint2*)g_Kh4)[dst] = kh;
    ((uint2*)g_Kl4)[dst] = kl;
    ((uint2*)g_Vh4)[dst] = vh;
    ((uint2*)g_Vl4)[dst] = vl;
}

// ===================== attention kernel: cp.async double-buffered pipeline =====================
__global__ __launch_bounds__(256, 2)
void attn_kernel(float* __restrict__ O)
{
    extern __shared__ __align__(16) char dsm[];
    const uint32_t sb = smem_u32(dsm);

    const int tid  = threadIdx.x;
    const int w    = tid >> 5;
    const int lane = tid & 31;
    const int qt = blockIdx.x, h = blockIdx.y, b = blockIdx.z;
    const int bh = b * HEADS + h;

    const int cnt   = g_kcnt[b];
    const int ntile = (cnt + 63) >> 6;
    const size_t tile_g0 = (size_t)bh * SEQ * DIM >> 3;   // uint4 base of this head

    // per-thread load pattern for tiles (512 uint4 per buffer, 2 per thread)
    const int li0 = tid,       lr0 = li0 >> 3, lo0 = li0 & 7;
    const int li1 = tid + 256, lr1 = li1 >> 3, lo1 = li1 & 7;
    const uint32_t ld0 = lr0 * RS + lo0 * 16;
    const uint32_t ld1 = lr1 * RS + lo1 * 16;

    // ---- stage Q (hi/lo) into buffer0 region via cp.async ----
    {
        const uint4* srcH = g_Qh4 + ((size_t)(bh * SEQ + qt * MQ) * DIM >> 3);
        const uint4* srcL = g_Ql4 + ((size_t)(bh * SEQ + qt * MQ) * DIM >> 3);
        #pragma unroll
        for (int i = 0; i < 4; i++) {
            int idx = tid + i * 256;          // 0..1023
            int r = idx >> 3, o = idx & 7;
            cpa16(sb + r * RS + o * 16,         srcH + idx);
            cpa16(sb + 18432 + r * RS + o * 16, srcL + idx);
        }
        CP_COMMIT();
        CP_WAIT(0);
    }
    __syncthreads();

    // ---- load Q fragments (A operands), 16 rows per warp ----
    const int qa_row  = (lane & 7) + ((lane & 8) ? 8 : 0);
    const int qa_colb = (lane & 16) ? 16 : 0;
    uint32_t qfh[4][4], qfl[4][4];
    {
        uint32_t baseH = sb + (16 * w + qa_row) * RS + qa_colb;
        uint32_t baseL = sb + 18432 + (16 * w + qa_row) * RS + qa_colb;
        #pragma unroll
        for (int ks = 0; ks < 4; ks++) {
            ldm4(qfh[ks], baseH + 32 * ks);
            ldm4(qfl[ks], baseL + 32 * ks);
        }
    }
    __syncthreads();   // buffer0 about to be overwritten by tile 0

    // ---- per-thread state ----
    float oacc[8][4];
    #pragma unroll
    for (int nt = 0; nt < 8; nt++)
        #pragma unroll
        for (int e = 0; e < 4; e++) oacc[nt][e] = 0.f;
    float m0 = -1e30f, m1 = -1e30f, l0 = 0.f, l1 = 0.f;

    const int   q4   = lane >> 2;
    const int   col0 = 2 * (lane & 3);
    const int   r0g  = qt * MQ + w * 16 + q4;
    const float fi0  = (float)r0g;
    const float L2E  = 1.4426950408889634f;
    const float C2   = 6.879347314016243e-7f;     // (2/2048^2) * log2(e)

    const int kb_row  = (lane & 7) + ((lane & 16) ? 8 : 0);
    const int kb_colb = (lane & 8) ? 16 : 0;
    const int vb_row  = (lane & 7) + ((lane & 8) ? 8 : 0);
    const int vb_colb = (lane & 16) ? 16 : 0;

    // issue tile loads into buffer `bsel`
    #define ISSUE_TILE(T, BSEL) do { \
        const uint32_t bb_ = sb + (BSEL) * BUF_BYTES; \
        size_t gb_ = tile_g0 + (size_t)(T) * NKV * 8; \
        cpa16(bb_ + ld0,         g_Kh4 + gb_ + li0); \
        cpa16(bb_ + ld1,         g_Kh4 + gb_ + li1); \
        cpa16(bb_ + 9216 + ld0,  g_Kl4 + gb_ + li0); \
        cpa16(bb_ + 9216 + ld1,  g_Kl4 + gb_ + li1); \
        cpa16(bb_ + 18432 + ld0, g_Vh4 + gb_ + li0); \
        cpa16(bb_ + 18432 + ld1, g_Vh4 + gb_ + li1); \
        cpa16(bb_ + 27648 + ld0, g_Vl4 + gb_ + li0); \
        cpa16(bb_ + 27648 + ld1, g_Vl4 + gb_ + li1); \
        if (tid < 16) cpa16(sb + FKT_OFF + (BSEL) * 256 + tid * 16, \
                            g_kidxf + b * SEQ + (T) * NKV + tid * 4); \
        CP_COMMIT(); \
    } while (0)

    ISSUE_TILE(0, 0);

    for (int t = 0; t < ntile; t++) {
        const int kt = t * NKV;
        const int bsel = t & 1;
        if (t + 1 < ntile) { ISSUE_TILE(t + 1, (t + 1) & 1); CP_WAIT(1); }
        else               { CP_WAIT(0); }
        __syncthreads();

        const uint32_t sKH = sb + bsel * BUF_BYTES;
        const uint32_t sKL = sKH + 9216;
        const uint32_t sVH = sKH + 18432;
        const uint32_t sVL = sKH + 27648;
        const float* fktp = (const float*)(dsm + FKT_OFF + bsel * 256);

        // ---- S = Q K^T (3-term compensated) ----
        float c[8][4];
        #pragma unroll
        for (int nt = 0; nt < 8; nt++)
            #pragma unroll
            for (int e = 0; e < 4; e++) c[nt][e] = 0.f;

        #pragma unroll
        for (int ks = 0; ks < 4; ks++) {
            uint32_t bb[8][2];
            #pragma unroll
            for (int g = 0; g < 4; g++) {
                uint32_t r4[4];
                ldm4(r4, sKH + (16 * g + kb_row) * RS + 32 * ks + kb_colb);
                bb[2*g][0] = r4[0]; bb[2*g][1] = r4[1];
                bb[2*g+1][0] = r4[2]; bb[2*g+1][1] = r4[3];
            }
            #pragma unroll
            for (int nt = 0; nt < 8; nt++) mma16816(c[nt], qfh[ks], bb[nt][0], bb[nt][1]);
            #pragma unroll
            for (int nt = 0; nt < 8; nt++) mma16816(c[nt], qfl[ks], bb[nt][0], bb[nt][1]);
            #pragma unroll
            for (int g = 0; g < 4; g++) {
                uint32_t r4[4];
                ldm4(r4, sKL + (16 * g + kb_row) * RS + 32 * ks + kb_colb);
                bb[2*g][0] = r4[0]; bb[2*g][1] = r4[1];
                bb[2*g+1][0] = r4[2]; bb[2*g+1][1] = r4[3];
            }
            #pragma unroll
            for (int nt = 0; nt < 8; nt++) mma16816(c[nt], qfh[ks], bb[nt][0], bb[nt][1]);
        }

        // ---- epilogue: tail mask, online softmax, decay; build P fragments ----
        const int lim = cnt - kt;       // >= 1; >= 64 except tail tile
        float mx0 = -1e30f, mx1 = -1e30f;
        #pragma unroll
        for (int nt = 0; nt < 8; nt++) {
            int j0 = 8 * nt + col0;
            if (j0 >= lim)     { c[nt][0] = -1e30f; c[nt][2] = -1e30f; }
            if (j0 + 1 >= lim) { c[nt][1] = -1e30f; c[nt][3] = -1e30f; }
            mx0 = fmaxf(mx0, fmaxf(c[nt][0], c[nt][1]));
            mx1 = fmaxf(mx1, fmaxf(c[nt][2], c[nt][3]));
        }
        mx0 = fmaxf(mx0, __shfl_xor_sync(0xffffffffu, mx0, 1));
        mx0 = fmaxf(mx0, __shfl_xor_sync(0xffffffffu, mx0, 2));
        mx1 = fmaxf(mx1, __shfl_xor_sync(0xffffffffu, mx1, 1));
        mx1 = fmaxf(mx1, __shfl_xor_sync(0xffffffffu, mx1, 2));

        float mn0 = fmaxf(m0, mx0), mn1 = fmaxf(m1, mx1);
        float corr0 = ex2f((m0 - mn0) * L2E);
        float corr1 = ex2f((m1 - mn1) * L2E);
        m0 = mn0; m1 = mn1;

        float lsA0 = 0.f, lsB0 = 0.f, lsA1 = 0.f, lsB1 = 0.f;   // two chains each
        uint32_t ph0[8], ph1[8], pl0[8], pl1[8];
        #pragma unroll
        for (int nt = 0; nt < 8; nt++) {
            float2 fk2 = *(const float2*)&fktp[8 * nt + col0];
            float rA0 = fi0 - fk2.x, rA1 = fi0 - fk2.y;
            float rB0 = rA0 + 8.f,   rB1 = rA1 + 8.f;
            float t00 = (c[nt][0] - m0) * L2E;
            float t01 = (c[nt][1] - m0) * L2E;
            float t10 = (c[nt][2] - m1) * L2E;
            float t11 = (c[nt][3] - m1) * L2E;
            lsA0 += ex2f(t00); lsB0 += ex2f(t01);
            lsA1 += ex2f(t10); lsB1 += ex2f(t11);
            float pd00 = ex2f(fmaf(-C2 * rA0, rA0, t00));
            float pd01 = ex2f(fmaf(-C2 * rA1, rA1, t01));
            float pd10 = ex2f(fmaf(-C2 * rB0, rB0, t10));
            float pd11 = ex2f(fmaf(-C2 * rB1, rB1, t11));
            uint32_t h0 = pack_bf16x2(pd01, pd00);
            uint32_t h1 = pack_bf16x2(pd11, pd10);
            float e00 = pd00 - __uint_as_float(h0 << 16);
            float e01 = pd01 - __uint_as_float(h0 & 0xFFFF0000u);
            float e10 = pd10 - __uint_as_float(h1 << 16);
            float e11 = pd11 - __uint_as_float(h1 & 0xFFFF0000u);
            ph0[nt] = h0; ph1[nt] = h1;
            pl0[nt] = pack_bf16x2(e01, e00);
            pl1[nt] = pack_bf16x2(e11, e10);
        }
        l0 = l0 * corr0 + (lsA0 + lsB0);
        l1 = l1 * corr1 + (lsA1 + lsB1);

        #pragma unroll
        for (int nt = 0; nt < 8; nt++) {
            oacc[nt][0] *= corr0; oacc[nt][1] *= corr0;
            oacc[nt][2] *= corr1; oacc[nt][3] *= corr1;
        }

        // ---- O += P V (3-term compensated), P from registers ----
        #pragma unroll
        for (int ksv = 0; ksv < 4; ksv++) {
            uint32_t ah[4] = { ph0[2*ksv], ph1[2*ksv], ph0[2*ksv+1], ph1[2*ksv+1] };
            uint32_t al[4] = { pl0[2*ksv], pl1[2*ksv], pl0[2*ksv+1], pl1[2*ksv+1] };
            uint32_t bb[8][2];
            #pragma unroll
            for (int g = 0; g < 4; g++) {
                uint32_t r4[4];
                ldm4t(r4, sVH + (16 * ksv + vb_row) * RS + 32 * g + vb_colb);
                bb[2*g][0] = r4[0]; bb[2*g][1] = r4[1];
                bb[2*g+1][0] = r4[2]; bb[2*g+1][1] = r4[3];
            }
            #pragma unroll
            for (int nt = 0; nt < 8; nt++) mma16816(oacc[nt], ah, bb[nt][0], bb[nt][1]);
            #pragma unroll
            for (int nt = 0; nt < 8; nt++) mma16816(oacc[nt], al, bb[nt][0], bb[nt][1]);
            #pragma unroll
            for (int g = 0; g < 4; g++) {
                uint32_t r4[4];
                ldm4t(r4, sVL + (16 * ksv + vb_row) * RS + 32 * g + vb_colb);
                bb[2*g][0] = r4[0]; bb[2*g][1] = r4[1];
                bb[2*g+1][0] = r4[2]; bb[2*g+1][1] = r4[3];
            }
            #pragma unroll
            for (int nt = 0; nt < 8; nt++) mma16816(oacc[nt], ah, bb[nt][0], bb[nt][1]);
        }
        __syncthreads();
    }

    // ---- reduce denominator across the quad ----
    l0 += __shfl_xor_sync(0xffffffffu, l0, 1);
    l0 += __shfl_xor_sync(0xffffffffu, l0, 2);
    l1 += __shfl_xor_sync(0xffffffffu, l1, 1);
    l1 += __shfl_xor_sync(0xffffffffu, l1, 2);

    // ---- write out ----
    float inv0 = (l0 > 0.f) ? (1.f / l0) : 0.f;
    float inv1 = (l1 > 0.f) ? (1.f / l1) : 0.f;
    float* o0 = O + ((size_t)bh * SEQ + r0g) * DIM;
    float* o1 = o0 + 8 * DIM;
    #pragma unroll
    for (int nt = 0; nt < 8; nt++) {
        int j = 8 * nt + col0;
        *(float2*)(o0 + j) = make_float2(oacc[nt][0] * inv0, oacc[nt][1] * inv0);
        *(float2*)(o1 + j) = make_float2(oacc[nt][2] * inv1, oacc[nt][3] * inv1);
    }
}

// ===================== host launch =====================
extern "C" void kernel_launch(void* const* d_in, const int* in_sizes, int n_in,
                              void* d_out, int out_size)
{
    const float* Q = (const float*)d_in[0];
    const float* K = (const float*)d_in[1];
    const float* V = (const float*)d_in[2];
    const unsigned int* mask = (const unsigned int*)d_in[3];
    float* O = (float*)d_out;

    static int configured = 0;
    if (!configured) {
        cudaFuncSetAttribute(attn_kernel, cudaFuncAttributeMaxDynamicSharedMemorySize,
                             DSMEM_BYTES);
        configured = 1;
    }

    mask_scan_kernel<<<BATCH, 1024>>>(mask);
    convert_q_kernel<<<TELEMS / 4 / 256, 256>>>(Q);
    gather_kv_kernel<<<TELEMS / 4 / 256, 256>>>(K, V);
    attn_kernel<<<dim3(SEQ / MQ, HEADS, BATCH), 256, DSMEM_BYTES>>>(O);
}

// round 11
// speedup vs baseline: 4.6184x; 1.0494x over previous
#include <cuda_runtime.h>
#include <cstdint>
#include <cstdlib>

// ===================== problem constants =====================
#define BATCH 4
#define HEADS 16
#define SEQ   2048
#define DIM   64
#define BH    (BATCH*HEADS)
#define TELEMS (BH*SEQ*DIM)      // 8,388,608
#define MQ    128                // queries per CTA
#define NKV   64                 // keys per tile
#define RS    144                // SMEM row stride bytes (72 bf16, conflict-free ldmatrix)

#define BUF_BYTES 36864          // 4 tiles x 64 rows x 144B
#define JIDX_OFF  (2*BUF_BYTES)              // 73728 (2 x 256B int tile indices)
#define DTAB_OFF  (JIDX_OFF + 512)           // 74240 (2048 x f32 decay table)
#define DSMEM_BYTES (DTAB_OFF + 8192)        // 82432

// ===================== device scratch =====================
__device__ uint4 g_Qh4[TELEMS/8];
__device__ uint4 g_Ql4[TELEMS/8];
__device__ uint4 g_Kh4[TELEMS/8];    // compacted key order
__device__ uint4 g_Kl4[TELEMS/8];
__device__ uint4 g_Vh4[TELEMS/8];
__device__ uint4 g_Vl4[TELEMS/8];
__device__ int   g_kcnt[BATCH];      // unmasked keys per batch
__device__ int   g_kidx[BATCH*SEQ];  // compacted -> original key index

// ===================== helpers =====================
__device__ __forceinline__ uint32_t smem_u32(const void* p) {
    uint32_t a;
    asm("{ .reg .u64 t; cvta.to.shared.u64 t, %1; cvt.u32.u64 %0, t; }" : "=r"(a) : "l"(p));
    return a;
}
__device__ __forceinline__ uint32_t pack_bf16x2(float hi, float lo) {
    uint32_t r;
    asm("cvt.rn.bf16x2.f32 %0, %1, %2;" : "=r"(r) : "f"(hi), "f"(lo));
    return r;
}
__device__ __forceinline__ float ex2f(float x) {
    float r;
    asm("ex2.approx.ftz.f32 %0, %1;" : "=f"(r) : "f"(x));
    return r;
}
__device__ __forceinline__ void ldm4(uint32_t r[4], uint32_t addr) {
    asm volatile("ldmatrix.sync.aligned.m8n8.x4.shared.b16 {%0,%1,%2,%3}, [%4];"
        : "=r"(r[0]), "=r"(r[1]), "=r"(r[2]), "=r"(r[3]) : "r"(addr));
}
__device__ __forceinline__ void ldm4t(uint32_t r[4], uint32_t addr) {
    asm volatile("ldmatrix.sync.aligned.m8n8.x4.trans.shared.b16 {%0,%1,%2,%3}, [%4];"
        : "=r"(r[0]), "=r"(r[1]), "=r"(r[2]), "=r"(r[3]) : "r"(addr));
}
__device__ __forceinline__ void mma16816(float c[4], const uint32_t a[4],
                                         uint32_t b0, uint32_t b1) {
    asm volatile(
        "mma.sync.aligned.m16n8k16.row.col.f32.bf16.bf16.f32 "
        "{%0,%1,%2,%3}, {%4,%5,%6,%7}, {%8,%9}, {%0,%1,%2,%3};"
        : "+f"(c[0]), "+f"(c[1]), "+f"(c[2]), "+f"(c[3])
        : "r"(a[0]), "r"(a[1]), "r"(a[2]), "r"(a[3]), "r"(b0), "r"(b1));
}
__device__ __forceinline__ void split4(float4 s, uint2& hi, uint2& lo) {
    uint32_t h0 = pack_bf16x2(s.y, s.x), h1 = pack_bf16x2(s.w, s.z);
    float r0 = s.x - __uint_as_float(h0 << 16);
    float r1 = s.y - __uint_as_float(h0 & 0xFFFF0000u);
    float r2 = s.z - __uint_as_float(h1 << 16);
    float r3 = s.w - __uint_as_float(h1 & 0xFFFF0000u);
    hi = make_uint2(h0, h1);
    lo = make_uint2(pack_bf16x2(r1, r0), pack_bf16x2(r3, r2));
}
__device__ __forceinline__ void cpa16(uint32_t saddr, const void* gaddr) {
    asm volatile("cp.async.cg.shared.global [%0], [%1], 16;" :: "r"(saddr), "l"(gaddr));
}
#define CP_COMMIT() asm volatile("cp.async.commit_group;" ::: "memory")
#define CP_WAIT(n)  asm volatile("cp.async.wait_group %0;" :: "n"(n) : "memory")

// ===================== kernel 1: compact unmasked key indices (per batch) =====================
__global__ void mask_scan_kernel(const unsigned int* __restrict__ mask) {
    __shared__ int wsum[32];
    __shared__ int woff[32];
    const int b = blockIdx.x;
    const int t = threadIdx.x;            // 1024 threads, 2 keys each
    const int lane = t & 31, wid = t >> 5;
    const unsigned int* mb = mask + (size_t)b * SEQ;

    int j0 = 2 * t, j1 = 2 * t + 1;
    int p0 = (mb[j0] == 0u) ? 1 : 0;      // keep unmasked
    int p1 = (mb[j1] == 0u) ? 1 : 0;
    int local = p0 + p1;

    int incl = local;
    #pragma unroll
    for (int d = 1; d < 32; d <<= 1) {
        int v = __shfl_up_sync(0xffffffffu, incl, d);
        if (lane >= d) incl += v;
    }
    if (lane == 31) wsum[wid] = incl;
    __syncthreads();
    if (wid == 0) {
        int v = wsum[lane];
        int iv = v;
        #pragma unroll
        for (int d = 1; d < 32; d <<= 1) {
            int u = __shfl_up_sync(0xffffffffu, iv, d);
            if (lane >= d) iv += u;
        }
        woff[lane] = iv - v;
        if (lane == 31) g_kcnt[b] = iv;
    }
    __syncthreads();

    int base = woff[wid] + (incl - local);
    if (p0) { g_kidx[b*SEQ + base] = j0; base++; }
    if (p1) { g_kidx[b*SEQ + base] = j1; }

    int cnt = g_kcnt[b];
    for (int j = cnt + t; j < SEQ; j += 1024) {
        g_kidx[b*SEQ + j] = 0;
    }
}

// ===================== kernel 2: split Q (pre-scaled) =====================
__global__ void convert_q_kernel(const float* __restrict__ Q) {
    size_t i4 = (size_t)blockIdx.x * 256 + threadIdx.x;
    float4 q = ((const float4*)Q)[i4];
    q.x *= 0.125f; q.y *= 0.125f; q.z *= 0.125f; q.w *= 0.125f;
    uint2 hi, lo;
    split4(q, hi, lo);
    ((uint2*)g_Qh4)[i4] = hi;
    ((uint2*)g_Ql4)[i4] = lo;
}

// ===================== kernel 3: gather + split K/V in compacted key order =====================
__global__ void gather_kv_kernel(const float* __restrict__ K, const float* __restrict__ V) {
    size_t gid = (size_t)blockIdx.x * 256 + threadIdx.x;   // over TELEMS/4 = 2^21 chunks
    int chunk = (int)(gid & 15);          // 16 float4 per row (DIM=64)
    int j     = (int)((gid >> 4) & (SEQ - 1));
    int bh    = (int)(gid >> 15);
    int b     = bh >> 4;
    int cnt   = g_kcnt[b];

    uint2 kh = make_uint2(0, 0), kl = kh, vh = kh, vl = kh;
    if (j < cnt) {
        int o = g_kidx[b*SEQ + j];
        size_t src = ((size_t)bh * SEQ + o) * 16 + chunk;
        split4(((const float4*)K)[src], kh, kl);
        split4(((const float4*)V)[src], vh, vl);
    }
    size_t dst = ((size_t)bh * SEQ + j) * 16 + chunk;
    ((uint2*)g_Kh4)[dst] = kh;
    ((uint2*)g_Kl4)[dst] = kl;
    ((uint2*)g_Vh4)[dst] = vh;
    ((uint2*)g_Vl4)[dst] = vl;
}

// ===================== attention kernel: static-max softmax + decay LUT =====================
__global__ __launch_bounds__(256, 2)
void attn_kernel(float* __restrict__ O)
{
    extern __shared__ __align__(16) char dsm[];
    const uint32_t sb = smem_u32(dsm);
    float* dtab = (float*)(dsm + DTAB_OFF);

    const int tid  = threadIdx.x;
    const int w    = tid >> 5;
    const int lane = tid & 31;
    const int qt = blockIdx.x, h = blockIdx.y, b = blockIdx.z;
    const int bh = b * HEADS + h;

    const int cnt   = g_kcnt[b];
    const int ntile = (cnt + 63) >> 6;
    const size_t tile_g0 = (size_t)bh * SEQ * DIM >> 3;   // uint4 base of this head

    const float L2E  = 1.4426950408889634f;
    const float C2   = 6.879347314016243e-7f;     // (2/2048^2) * log2(e)

    // per-thread load pattern for tiles (512 uint4 per buffer, 2 per thread)
    const int li0 = tid,       lr0 = li0 >> 3, lo0 = li0 & 7;
    const int li1 = tid + 256, lr1 = li1 >> 3, lo1 = li1 & 7;
    const uint32_t ld0 = lr0 * RS + lo0 * 16;
    const uint32_t ld1 = lr1 * RS + lo1 * 16;

    // ---- stage Q (hi/lo) into buffer0 region via cp.async; fill decay table meanwhile ----
    {
        const uint4* srcH = g_Qh4 + ((size_t)(bh * SEQ + qt * MQ) * DIM >> 3);
        const uint4* srcL = g_Ql4 + ((size_t)(bh * SEQ + qt * MQ) * DIM >> 3);
        #pragma unroll
        for (int i = 0; i < 4; i++) {
            int idx = tid + i * 256;          // 0..1023
            int r = idx >> 3, o = idx & 7;
            cpa16(sb + r * RS + o * 16,         srcH + idx);
            cpa16(sb + 18432 + r * RS + o * 16, srcL + idx);
        }
        CP_COMMIT();
        #pragma unroll
        for (int r = 0; r < 8; r++) {
            int idx = tid + r * 256;          // 0..2047
            float fr = (float)idx;
            dtab[idx] = ex2f(-C2 * fr * fr);
        }
        CP_WAIT(0);
    }
    __syncthreads();

    // ---- load Q fragments (A operands), 16 rows per warp ----
    const int qa_row  = (lane & 7) + ((lane & 8) ? 8 : 0);
    const int qa_colb = (lane & 16) ? 16 : 0;
    uint32_t qfh[4][4], qfl[4][4];
    {
        uint32_t baseH = sb + (16 * w + qa_row) * RS + qa_colb;
        uint32_t baseL = sb + 18432 + (16 * w + qa_row) * RS + qa_colb;
        #pragma unroll
        for (int ks = 0; ks < 4; ks++) {
            ldm4(qfh[ks], baseH + 32 * ks);
            ldm4(qfl[ks], baseL + 32 * ks);
        }
    }
    __syncthreads();   // buffer0 about to be overwritten by tile 0

    // ---- per-thread state ----
    float oacc[8][4];
    #pragma unroll
    for (int nt = 0; nt < 8; nt++)
        #pragma unroll
        for (int e = 0; e < 4; e++) oacc[nt][e] = 0.f;
    float l0 = 0.f, l1 = 0.f;

    const int   q4   = lane >> 2;
    const int   col0 = 2 * (lane & 3);
    const int   r0g  = qt * MQ + w * 16 + q4;

    const int kb_row  = (lane & 7) + ((lane & 16) ? 8 : 0);
    const int kb_colb = (lane & 8) ? 16 : 0;
    const int vb_row  = (lane & 7) + ((lane & 8) ? 8 : 0);
    const int vb_colb = (lane & 16) ? 16 : 0;

    // issue tile loads into buffer `bsel`
    #define ISSUE_TILE(T, BSEL) do { \
        const uint32_t bb_ = sb + (BSEL) * BUF_BYTES; \
        size_t gb_ = tile_g0 + (size_t)(T) * NKV * 8; \
        cpa16(bb_ + ld0,         g_Kh4 + gb_ + li0); \
        cpa16(bb_ + ld1,         g_Kh4 + gb_ + li1); \
        cpa16(bb_ + 9216 + ld0,  g_Kl4 + gb_ + li0); \
        cpa16(bb_ + 9216 + ld1,  g_Kl4 + gb_ + li1); \
        cpa16(bb_ + 18432 + ld0, g_Vh4 + gb_ + li0); \
        cpa16(bb_ + 18432 + ld1, g_Vh4 + gb_ + li1); \
        cpa16(bb_ + 27648 + ld0, g_Vl4 + gb_ + li0); \
        cpa16(bb_ + 27648 + ld1, g_Vl4 + gb_ + li1); \
        if (tid < 16) cpa16(sb + JIDX_OFF + (BSEL) * 256 + tid * 16, \
                            g_kidx + b * SEQ + (T) * NKV + tid * 4); \
        CP_COMMIT(); \
    } while (0)

    ISSUE_TILE(0, 0);

    for (int t = 0; t < ntile; t++) {
        const int kt = t * NKV;
        const int bsel = t & 1;
        if (t + 1 < ntile) { ISSUE_TILE(t + 1, (t + 1) & 1); CP_WAIT(1); }
        else               { CP_WAIT(0); }
        __syncthreads();

        const uint32_t sKH = sb + bsel * BUF_BYTES;
        const uint32_t sKL = sKH + 9216;
        const uint32_t sVH = sKH + 18432;
        const uint32_t sVL = sKH + 27648;
        const int* jidx = (const int*)(dsm + JIDX_OFF + bsel * 256);

        // ---- S = Q K^T (3-term compensated) ----
        float c[8][4];
        #pragma unroll
        for (int nt = 0; nt < 8; nt++)
            #pragma unroll
            for (int e = 0; e < 4; e++) c[nt][e] = 0.f;

        #pragma unroll
        for (int ks = 0; ks < 4; ks++) {
            uint32_t bb[8][2];
            #pragma unroll
            for (int g = 0; g < 4; g++) {
                uint32_t r4[4];
                ldm4(r4, sKH + (16 * g + kb_row) * RS + 32 * ks + kb_colb);
                bb[2*g][0] = r4[0]; bb[2*g][1] = r4[1];
                bb[2*g+1][0] = r4[2]; bb[2*g+1][1] = r4[3];
            }
            #pragma unroll
            for (int nt = 0; nt < 8; nt++) mma16816(c[nt], qfh[ks], bb[nt][0], bb[nt][1]);
            #pragma unroll
            for (int nt = 0; nt < 8; nt++) mma16816(c[nt], qfl[ks], bb[nt][0], bb[nt][1]);
            #pragma unroll
            for (int g = 0; g < 4; g++) {
                uint32_t r4[4];
                ldm4(r4, sKL + (16 * g + kb_row) * RS + 32 * ks + kb_colb);
                bb[2*g][0] = r4[0]; bb[2*g][1] = r4[1];
                bb[2*g+1][0] = r4[2]; bb[2*g+1][1] = r4[3];
            }
            #pragma unroll
            for (int nt = 0; nt < 8; nt++) mma16816(c[nt], qfh[ks], bb[nt][0], bb[nt][1]);
        }

        // ---- epilogue: static-max softmax + LUT decay; build P fragments ----
        const int lim = cnt - kt;       // >= 1; >= 64 except tail tile
        float lsA0 = 0.f, lsB0 = 0.f, lsA1 = 0.f, lsB1 = 0.f;
        uint32_t ph0[8], ph1[8], pl0[8], pl1[8];
        #pragma unroll
        for (int nt = 0; nt < 8; nt++) {
            int j0i = 8 * nt + col0;
            if (j0i >= lim)     { c[nt][0] = -1e30f; c[nt][2] = -1e30f; }
            if (j0i + 1 >= lim) { c[nt][1] = -1e30f; c[nt][3] = -1e30f; }

            int2 j2 = *(const int2*)&jidx[j0i];
            float dA0 = dtab[abs(r0g     - j2.x)];
            float dA1 = dtab[abs(r0g     - j2.y)];
            float dB0 = dtab[abs(r0g + 8 - j2.x)];
            float dB1 = dtab[abs(r0g + 8 - j2.y)];

            float p00 = ex2f(c[nt][0] * L2E);
            float p01 = ex2f(c[nt][1] * L2E);
            float p10 = ex2f(c[nt][2] * L2E);
            float p11 = ex2f(c[nt][3] * L2E);
            lsA0 += p00; lsB0 += p01;
            lsA1 += p10; lsB1 += p11;

            float pd00 = p00 * dA0;
            float pd01 = p01 * dA1;
            float pd10 = p10 * dB0;
            float pd11 = p11 * dB1;

            uint32_t h0 = pack_bf16x2(pd01, pd00);
            uint32_t h1 = pack_bf16x2(pd11, pd10);
            float e00 = pd00 - __uint_as_float(h0 << 16);
            float e01 = pd01 - __uint_as_float(h0 & 0xFFFF0000u);
            float e10 = pd10 - __uint_as_float(h1 << 16);
            float e11 = pd11 - __uint_as_float(h1 & 0xFFFF0000u);
            ph0[nt] = h0; ph1[nt] = h1;
            pl0[nt] = pack_bf16x2(e01, e00);
            pl1[nt] = pack_bf16x2(e11, e10);
        }
        l0 += lsA0 + lsB0;
        l1 += lsA1 + lsB1;

        // ---- O += P V (3-term compensated), P from registers ----
        #pragma unroll
        for (int ksv = 0; ksv < 4; ksv++) {
            uint32_t ah[4] = { ph0[2*ksv], ph1[2*ksv], ph0[2*ksv+1], ph1[2*ksv+1] };
            uint32_t al[4] = { pl0[2*ksv], pl1[2*ksv], pl0[2*ksv+1], pl1[2*ksv+1] };
            uint32_t bb[8][2];
            #pragma unroll
            for (int g = 0; g < 4; g++) {
                uint32_t r4[4];
                ldm4t(r4, sVH + (16 * ksv + vb_row) * RS + 32 * g + vb_colb);
                bb[2*g][0] = r4[0]; bb[2*g][1] = r4[1];
                bb[2*g+1][0] = r4[2]; bb[2*g+1][1] = r4[3];
            }
            #pragma unroll
            for (int nt = 0; nt < 8; nt++) mma16816(oacc[nt], ah, bb[nt][0], bb[nt][1]);
            #pragma unroll
            for (int nt = 0; nt < 8; nt++) mma16816(oacc[nt], al, bb[nt][0], bb[nt][1]);
            #pragma unroll
            for (int g = 0; g < 4; g++) {
                uint32_t r4[4];
                ldm4t(r4, sVL + (16 * ksv + vb_row) * RS + 32 * g + vb_colb);
                bb[2*g][0] = r4[0]; bb[2*g][1] = r4[1];
                bb[2*g+1][0] = r4[2]; bb[2*g+1][1] = r4[3];
            }
            #pragma unroll
            for (int nt = 0; nt < 8; nt++) mma16816(oacc[nt], ah, bb[nt][0], bb[nt][1]);
        }
        __syncthreads();
    }

    // ---- reduce denominator across the quad ----
    l0 += __shfl_xor_sync(0xffffffffu, l0, 1);
    l0 += __shfl_xor_sync(0xffffffffu, l0, 2);
    l1 += __shfl_xor_sync(0xffffffffu, l1, 1);
    l1 += __shfl_xor_sync(0xffffffffu, l1, 2);

    // ---- write out ----
    float inv0 = (l0 > 0.f) ? (1.f / l0) : 0.f;
    float inv1 = (l1 > 0.f) ? (1.f / l1) : 0.f;
    float* o0 = O + ((size_t)bh * SEQ + r0g) * DIM;
    float* o1 = o0 + 8 * DIM;
    #pragma unroll
    for (int nt = 0; nt < 8; nt++) {
        int j = 8 * nt + col0;
        *(float2*)(o0 + j) = make_float2(oacc[nt][0] * inv0, oacc[nt][1] * inv0);
        *(float2*)(o1 + j) = make_float2(oacc[nt][2] * inv1, oacc[nt][3] * inv1);
    }
}

// ===================== host launch =====================
extern "C" void kernel_launch(void* const* d_in, const int* in_sizes, int n_in,
                              void* d_out, int out_size)
{
    const float* Q = (const float*)d_in[0];
    const float* K = (const float*)d_in[1];
    const float* V = (const float*)d_in[2];
    const unsigned int* mask = (const unsigned int*)d_in[3];
    float* O = (float*)d_out;

    static int configured = 0;
    if (!configured) {
        cudaFuncSetAttribute(attn_kernel, cudaFuncAttributeMaxDynamicSharedMemorySize,
                             DSMEM_BYTES);
        configured = 1;
    }

    mask_scan_kernel<<<BATCH, 1024>>>(mask);
    convert_q_kernel<<<TELEMS / 4 / 256, 256>>>(Q);
    gather_kv_kernel<<<TELEMS / 4 / 256, 256>>>(K, V);
    attn_kernel<<<dim3(SEQ / MQ, HEADS, BATCH), 256, DSMEM_BYTES>>>(O);
}

// round 13
// speedup vs baseline: 4.7399x; 1.0263x over previous
#include <cuda_runtime.h>
#include <cstdint>

// ===================== problem constants =====================
#define BATCH 4
#define HEADS 16
#define SEQ   2048
#define DIM   64
#define BH    (BATCH*HEADS)
#define TELEMS (BH*SEQ*DIM)      // 8,388,608
#define MQ    128                // queries per CTA
#define NKV   64                 // keys per tile
#define RS    144                // SMEM row stride bytes (72 bf16, conflict-free ldmatrix)

#define BUF_BYTES 36864          // 4 tiles x 64 rows x 144B
#define FKT_OFF   (2*BUF_BYTES)              // 73728 (2 x 256B float tile indices)
#define DSMEM_BYTES (FKT_OFF + 512)          // 74240

// ===================== device scratch =====================
__device__ uint4 g_Qh4[TELEMS/8];
__device__ uint4 g_Ql4[TELEMS/8];
__device__ uint4 g_Kh4[TELEMS/8];    // compacted key order
__device__ uint4 g_Kl4[TELEMS/8];
__device__ uint4 g_Vh4[TELEMS/8];
__device__ uint4 g_Vl4[TELEMS/8];
__device__ int   g_kcnt[BATCH];      // unmasked keys per batch
__device__ int   g_kidx[BATCH*SEQ];  // compacted -> original key index
__device__ float g_kidxf[BATCH*SEQ]; // same, as float (for decay)

// ===================== helpers =====================
__device__ __forceinline__ uint32_t smem_u32(const void* p) {
    uint32_t a;
    asm("{ .reg .u64 t; cvta.to.shared.u64 t, %1; cvt.u32.u64 %0, t; }" : "=r"(a) : "l"(p));
    return a;
}
__device__ __forceinline__ uint32_t pack_bf16x2(float hi, float lo) {
    uint32_t r;
    asm("cvt.rn.bf16x2.f32 %0, %1, %2;" : "=r"(r) : "f"(hi), "f"(lo));
    return r;
}
__device__ __forceinline__ float ex2f(float x) {
    float r;
    asm("ex2.approx.ftz.f32 %0, %1;" : "=f"(r) : "f"(x));
    return r;
}
__device__ __forceinline__ void ldm4(uint32_t r[4], uint32_t addr) {
    asm volatile("ldmatrix.sync.aligned.m8n8.x4.shared.b16 {%0,%1,%2,%3}, [%4];"
        : "=r"(r[0]), "=r"(r[1]), "=r"(r[2]), "=r"(r[3]) : "r"(addr));
}
__device__ __forceinline__ void ldm4t(uint32_t r[4], uint32_t addr) {
    asm volatile("ldmatrix.sync.aligned.m8n8.x4.trans.shared.b16 {%0,%1,%2,%3}, [%4];"
        : "=r"(r[0]), "=r"(r[1]), "=r"(r[2]), "=r"(r[3]) : "r"(addr));
}
__device__ __forceinline__ void mma16816(float c[4], const uint32_t a[4],
                                         uint32_t b0, uint32_t b1) {
    asm volatile(
        "mma.sync.aligned.m16n8k16.row.col.f32.bf16.bf16.f32 "
        "{%0,%1,%2,%3}, {%4,%5,%6,%7}, {%8,%9}, {%0,%1,%2,%3};"
        : "+f"(c[0]), "+f"(c[1]), "+f"(c[2]), "+f"(c[3])
        : "r"(a[0]), "r"(a[1]), "r"(a[2]), "r"(a[3]), "r"(b0), "r"(b1));
}
__device__ __forceinline__ void split4(float4 s, uint2& hi, uint2& lo) {
    uint32_t h0 = pack_bf16x2(s.y, s.x), h1 = pack_bf16x2(s.w, s.z);
    float r0 = s.x - __uint_as_float(h0 << 16);
    float r1 = s.y - __uint_as_float(h0 & 0xFFFF0000u);
    float r2 = s.z - __uint_as_float(h1 << 16);
    float r3 = s.w - __uint_as_float(h1 & 0xFFFF0000u);
    hi = make_uint2(h0, h1);
    lo = make_uint2(pack_bf16x2(r1, r0), pack_bf16x2(r3, r2));
}
__device__ __forceinline__ void cpa16(uint32_t saddr, const void* gaddr) {
    asm volatile("cp.async.cg.shared.global [%0], [%1], 16;" :: "r"(saddr), "l"(gaddr));
}
#define CP_COMMIT() asm volatile("cp.async.commit_group;" ::: "memory")
#define CP_WAIT(n)  asm volatile("cp.async.wait_group %0;" :: "n"(n) : "memory")

// ===================== kernel 1: compact unmasked key indices (per batch) =====================
__global__ void mask_scan_kernel(const unsigned int* __restrict__ mask) {
    __shared__ int wsum[32];
    __shared__ int woff[32];
    const int b = blockIdx.x;
    const int t = threadIdx.x;            // 1024 threads, 2 keys each
    const int lane = t & 31, wid = t >> 5;
    const unsigned int* mb = mask + (size_t)b * SEQ;

    int j0 = 2 * t, j1 = 2 * t + 1;
    int p0 = (mb[j0] == 0u) ? 1 : 0;      // keep unmasked
    int p1 = (mb[j1] == 0u) ? 1 : 0;
    int local = p0 + p1;

    int incl = local;
    #pragma unroll
    for (int d = 1; d < 32; d <<= 1) {
        int v = __shfl_up_sync(0xffffffffu, incl, d);
        if (lane >= d) incl += v;
    }
    if (lane == 31) wsum[wid] = incl;
    __syncthreads();
    if (wid == 0) {
        int v = wsum[lane];
        int iv = v;
        #pragma unroll
        for (int d = 1; d < 32; d <<= 1) {
            int u = __shfl_up_sync(0xffffffffu, iv, d);
            if (lane >= d) iv += u;
        }
        woff[lane] = iv - v;
        if (lane == 31) g_kcnt[b] = iv;
    }
    __syncthreads();

    int base = woff[wid] + (incl - local);
    if (p0) { g_kidx[b*SEQ + base] = j0; g_kidxf[b*SEQ + base] = (float)j0; base++; }
    if (p1) { g_kidx[b*SEQ + base] = j1; g_kidxf[b*SEQ + base] = (float)j1; }

    int cnt = g_kcnt[b];
    for (int j = cnt + t; j < SEQ; j += 1024) {
        g_kidx[b*SEQ + j]  = 0;
        g_kidxf[b*SEQ + j] = 0.f;
    }
}

// ===================== kernel 2: split Q (pre-scaled) =====================
__global__ void convert_q_kernel(const float* __restrict__ Q) {
    size_t i4 = (size_t)blockIdx.x * 256 + threadIdx.x;
    float4 q = ((const float4*)Q)[i4];
    q.x *= 0.125f; q.y *= 0.125f; q.z *= 0.125f; q.w *= 0.125f;
    uint2 hi, lo;
    split4(q, hi, lo);
    ((uint2*)g_Qh4)[i4] = hi;
    ((uint2*)g_Ql4)[i4] = lo;
}

// ===================== kernel 3: gather + split K/V in compacted key order =====================
__global__ void gather_kv_kernel(const float* __restrict__ K, const float* __restrict__ V) {
    size_t gid = (size_t)blockIdx.x * 256 + threadIdx.x;   // over TELEMS/4 = 2^21 chunks
    int chunk = (int)(gid & 15);          // 16 float4 per row (DIM=64)
    int j     = (int)((gid >> 4) & (SEQ - 1));
    int bh    = (int)(gid >> 15);
    int b     = bh >> 4;
    int cnt   = g_kcnt[b];

    uint2 kh = make_uint2(0, 0), kl = kh, vh = kh, vl = kh;
    if (j < cnt) {
        int o = g_kidx[b*SEQ + j];
        size_t src = ((size_t)bh * SEQ + o) * 16 + chunk;
        split4(((const float4*)K)[src], kh, kl);
        split4(((const float4*)V)[src], vh, vl);
    }
    size_t dst = ((size_t)bh * SEQ + j) * 16 + chunk;
    ((uint2*)g_Kh4)[dst] = kh;
    ((uint2*)g_Kl4)[dst] = kl;
    ((uint2*)g_Vh4)[dst] = vh;
    ((uint2*)g_Vl4)[dst] = vl;
}

// ===================== attention kernel: static-max softmax, fused decay, interleaved PV =====================
__global__ __launch_bounds__(256, 2)
void attn_kernel(float* __restrict__ O)
{
    extern __shared__ __align__(16) char dsm[];
    const uint32_t sb = smem_u32(dsm);

    const int tid  = threadIdx.x;
    const int w    = tid >> 5;
    const int lane = tid & 31;
    const int qt = blockIdx.x, h = blockIdx.y, b = blockIdx.z;
    const int bh = b * HEADS + h;

    const int cnt   = g_kcnt[b];
    const int ntile = (cnt + 63) >> 6;
    const size_t tile_g0 = (size_t)bh * SEQ * DIM >> 3;   // uint4 base of this head

    const float L2E  = 1.4426950408889634f;
    const float C2   = 6.879347314016243e-7f;     // (2/2048^2) * log2(e)

    // per-thread load pattern for tiles (512 uint4 per buffer, 2 per thread)
    const int li0 = tid,       lr0 = li0 >> 3, lo0 = li0 & 7;
    const int li1 = tid + 256, lr1 = li1 >> 3, lo1 = li1 & 7;
    const uint32_t ld0 = lr0 * RS + lo0 * 16;
    const uint32_t ld1 = lr1 * RS + lo1 * 16;

    // ---- stage Q (hi/lo) into buffer0 region via cp.async ----
    {
        const uint4* srcH = g_Qh4 + ((size_t)(bh * SEQ + qt * MQ) * DIM >> 3);
        const uint4* srcL = g_Ql4 + ((size_t)(bh * SEQ + qt * MQ) * DIM >> 3);
        #pragma unroll
        for (int i = 0; i < 4; i++) {
            int idx = tid + i * 256;          // 0..1023
            int r = idx >> 3, o = idx & 7;
            cpa16(sb + r * RS + o * 16,         srcH + idx);
            cpa16(sb + 18432 + r * RS + o * 16, srcL + idx);
        }
        CP_COMMIT();
        CP_WAIT(0);
    }
    __syncthreads();

    // ---- load Q fragments (A operands), 16 rows per warp ----
    const int qa_row  = (lane & 7) + ((lane & 8) ? 8 : 0);
    const int qa_colb = (lane & 16) ? 16 : 0;
    uint32_t qfh[4][4], qfl[4][4];
    {
        uint32_t baseH = sb + (16 * w + qa_row) * RS + qa_colb;
        uint32_t baseL = sb + 18432 + (16 * w + qa_row) * RS + qa_colb;
        #pragma unroll
        for (int ks = 0; ks < 4; ks++) {
            ldm4(qfh[ks], baseH + 32 * ks);
            ldm4(qfl[ks], baseL + 32 * ks);
        }
    }
    __syncthreads();   // buffer0 about to be overwritten by tile 0

    // ---- per-thread state ----
    float oacc[8][4];
    #pragma unroll
    for (int nt = 0; nt < 8; nt++)
        #pragma unroll
        for (int e = 0; e < 4; e++) oacc[nt][e] = 0.f;
    float l0 = 0.f, l1 = 0.f;

    const int   q4   = lane >> 2;
    const int   col0 = 2 * (lane & 3);
    const int   r0g  = qt * MQ + w * 16 + q4;
    const float fi0  = (float)r0g;

    const int kb_row  = (lane & 7) + ((lane & 16) ? 8 : 0);
    const int kb_colb = (lane & 8) ? 16 : 0;
    const int vb_row  = (lane & 7) + ((lane & 8) ? 8 : 0);
    const int vb_colb = (lane & 16) ? 16 : 0;

    // issue tile loads into buffer `bsel`
    #define ISSUE_TILE(T, BSEL) do { \
        const uint32_t bb_ = sb + (BSEL) * BUF_BYTES; \
        size_t gb_ = tile_g0 + (size_t)(T) * NKV * 8; \
        cpa16(bb_ + ld0,         g_Kh4 + gb_ + li0); \
        cpa16(bb_ + ld1,         g_Kh4 + gb_ + li1); \
        cpa16(bb_ + 9216 + ld0,  g_Kl4 + gb_ + li0); \
        cpa16(bb_ + 9216 + ld1,  g_Kl4 + gb_ + li1); \
        cpa16(bb_ + 18432 + ld0, g_Vh4 + gb_ + li0); \
        cpa16(bb_ + 18432 + ld1, g_Vh4 + gb_ + li1); \
        cpa16(bb_ + 27648 + ld0, g_Vl4 + gb_ + li0); \
        cpa16(bb_ + 27648 + ld1, g_Vl4 + gb_ + li1); \
        if (tid < 16) cpa16(sb + FKT_OFF + (BSEL) * 256 + tid * 16, \
                            g_kidxf + b * SEQ + (T) * NKV + tid * 4); \
        CP_COMMIT(); \
    } while (0)

    ISSUE_TILE(0, 0);

    for (int t = 0; t < ntile; t++) {
        const int kt = t * NKV;
        const int bsel = t & 1;
        if (t + 1 < ntile) { ISSUE_TILE(t + 1, (t + 1) & 1); CP_WAIT(1); }
        else               { CP_WAIT(0); }
        __syncthreads();

        const uint32_t sKH = sb + bsel * BUF_BYTES;
        const uint32_t sKL = sKH + 9216;
        const uint32_t sVH = sKH + 18432;
        const uint32_t sVL = sKH + 27648;
        const float* fktp = (const float*)(dsm + FKT_OFF + bsel * 256);

        // ---- S = Q K^T (3-term compensated) ----
        float c[8][4];
        #pragma unroll
        for (int nt = 0; nt < 8; nt++)
            #pragma unroll
            for (int e = 0; e < 4; e++) c[nt][e] = 0.f;

        #pragma unroll
        for (int ks = 0; ks < 4; ks++) {
            uint32_t bb[8][2];
            #pragma unroll
            for (int g = 0; g < 4; g++) {
                uint32_t r4[4];
                ldm4(r4, sKH + (16 * g + kb_row) * RS + 32 * ks + kb_colb);
                bb[2*g][0] = r4[0]; bb[2*g][1] = r4[1];
                bb[2*g+1][0] = r4[2]; bb[2*g+1][1] = r4[3];
            }
            #pragma unroll
            for (int nt = 0; nt < 8; nt++) mma16816(c[nt], qfh[ks], bb[nt][0], bb[nt][1]);
            #pragma unroll
            for (int nt = 0; nt < 8; nt++) mma16816(c[nt], qfl[ks], bb[nt][0], bb[nt][1]);
            #pragma unroll
            for (int g = 0; g < 4; g++) {
                uint32_t r4[4];
                ldm4(r4, sKL + (16 * g + kb_row) * RS + 32 * ks + kb_colb);
                bb[2*g][0] = r4[0]; bb[2*g][1] = r4[1];
                bb[2*g+1][0] = r4[2]; bb[2*g+1][1] = r4[3];
            }
            #pragma unroll
            for (int nt = 0; nt < 8; nt++) mma16816(c[nt], qfh[ks], bb[nt][0], bb[nt][1]);
        }

        // ---- tail masking: only the last tile has partial keys ----
        if (t == ntile - 1) {
            const int lim = cnt - kt;
            #pragma unroll
            for (int nt = 0; nt < 8; nt++) {
                int j0i = 8 * nt + col0;
                if (j0i >= lim)     { c[nt][0] = -1e30f; c[nt][2] = -1e30f; }
                if (j0i + 1 >= lim) { c[nt][1] = -1e30f; c[nt][3] = -1e30f; }
            }
        }

        // ---- interleaved: per k-step produce P fragments then PV MMAs ----
        float lsA0 = 0.f, lsB0 = 0.f, lsA1 = 0.f, lsB1 = 0.f;
        #pragma unroll
        for (int ksv = 0; ksv < 4; ksv++) {
            uint32_t ah[4], al[4];
            #pragma unroll
            for (int half = 0; half < 2; half++) {
                const int nt = 2 * ksv + half;
                float2 fk2 = *(const float2*)&fktp[8 * nt + col0];
                float rA0 = fi0 - fk2.x, rA1 = fi0 - fk2.y;
                float rB0 = rA0 + 8.f,   rB1 = rA1 + 8.f;
                float t00 = c[nt][0] * L2E;
                float t01 = c[nt][1] * L2E;
                float t10 = c[nt][2] * L2E;
                float t11 = c[nt][3] * L2E;
                float p00 = ex2f(t00);
                float p01 = ex2f(t01);
                float p10 = ex2f(t10);
                float p11 = ex2f(t11);
                lsA0 += p00; lsB0 += p01;
                lsA1 += p10; lsB1 += p11;
                float pd00 = ex2f(fmaf(-C2 * rA0, rA0, t00));
                float pd01 = ex2f(fmaf(-C2 * rA1, rA1, t01));
                float pd10 = ex2f(fmaf(-C2 * rB0, rB0, t10));
                float pd11 = ex2f(fmaf(-C2 * rB1, rB1, t11));
                uint32_t h0 = pack_bf16x2(pd01, pd00);
                uint32_t h1 = pack_bf16x2(pd11, pd10);
                float e00 = pd00 - __uint_as_float(h0 << 16);
                float e01 = pd01 - __uint_as_float(h0 & 0xFFFF0000u);
                float e10 = pd10 - __uint_as_float(h1 << 16);
                float e11 = pd11 - __uint_as_float(h1 & 0xFFFF0000u);
                ah[2*half]     = h0;
                ah[2*half + 1] = h1;
                al[2*half]     = pack_bf16x2(e01, e00);
                al[2*half + 1] = pack_bf16x2(e11, e10);
            }
            uint32_t bb[8][2];
            #pragma unroll
            for (int g = 0; g < 4; g++) {
                uint32_t r4[4];
                ldm4t(r4, sVH + (16 * ksv + vb_row) * RS + 32 * g + vb_colb);
                bb[2*g][0] = r4[0]; bb[2*g][1] = r4[1];
                bb[2*g+1][0] = r4[2]; bb[2*g+1][1] = r4[3];
            }
            #pragma unroll
            for (int nt = 0; nt < 8; nt++) mma16816(oacc[nt], ah, bb[nt][0], bb[nt][1]);
            #pragma unroll
            for (int nt = 0; nt < 8; nt++) mma16816(oacc[nt], al, bb[nt][0], bb[nt][1]);
            #pragma unroll
            for (int g = 0; g < 4; g++) {
                uint32_t r4[4];
                ldm4t(r4, sVL + (16 * ksv + vb_row) * RS + 32 * g + vb_colb);
                bb[2*g][0] = r4[0]; bb[2*g][1] = r4[1];
                bb[2*g+1][0] = r4[2]; bb[2*g+1][1] = r4[3];
            }
            #pragma unroll
            for (int nt = 0; nt < 8; nt++) mma16816(oacc[nt], ah, bb[nt][0], bb[nt][1]);
        }
        l0 += lsA0 + lsB0;
        l1 += lsA1 + lsB1;
        __syncthreads();
    }

    // ---- reduce denominator across the quad ----
    l0 += __shfl_xor_sync(0xffffffffu, l0, 1);
    l0 += __shfl_xor_sync(0xffffffffu, l0, 2);
    l1 += __shfl_xor_sync(0xffffffffu, l1, 1);
    l1 += __shfl_xor_sync(0xffffffffu, l1, 2);

    // ---- write out ----
    float inv0 = (l0 > 0.f) ? (1.f / l0) : 0.f;
    float inv1 = (l1 > 0.f) ? (1.f / l1) : 0.f;
    float* o0 = O + ((size_t)bh * SEQ + r0g) * DIM;
    float* o1 = o0 + 8 * DIM;
    #pragma unroll
    for (int nt = 0; nt < 8; nt++) {
        int j = 8 * nt + col0;
        *(float2*)(o0 + j) = make_float2(oacc[nt][0] * inv0, oacc[nt][1] * inv0);
        *(float2*)(o1 + j) = make_float2(oacc[nt][2] * inv1, oacc[nt][3] * inv1);
    }
}

// ===================== host launch =====================
extern "C" void kernel_launch(void* const* d_in, const int* in_sizes, int n_in,
                              void* d_out, int out_size)
{
    const float* Q = (const float*)d_in[0];
    const float* K = (const float*)d_in[1];
    const float* V = (const float*)d_in[2];
    const unsigned int* mask = (const unsigned int*)d_in[3];
    float* O = (float*)d_out;

    static int configured = 0;
    if (!configured) {
        cudaFuncSetAttribute(attn_kernel, cudaFuncAttributeMaxDynamicSharedMemorySize,
                             DSMEM_BYTES);
        configured = 1;
    }

    mask_scan_kernel<<<BATCH, 1024>>>(mask);
    convert_q_kernel<<<TELEMS / 4 / 256, 256>>>(Q);
    gather_kv_kernel<<<TELEMS / 4 / 256, 256>>>(K, V);
    attn_kernel<<<dim3(SEQ / MQ, HEADS, BATCH), 256, DSMEM_BYTES>>>(O);
}

// round 14
// speedup vs baseline: 6.5609x; 1.3842x over previous
#include <cuda_runtime.h>
#include <cstdint>

// ===================== problem constants =====================
#define BATCH 4
#define HEADS 16
#define SEQ   2048
#define DIM   64
#define BH    (BATCH*HEADS)
#define TELEMS (BH*SEQ*DIM)      // 8,388,608
#define MQ    128                // queries per CTA
#define NKV   64                 // keys per tile
#define RS    144                // SMEM row stride bytes (72 f16, conflict-free ldmatrix)

#define BUF_BYTES 18432          // 2 tiles (KH,VH) x 64 rows x 144B
#define NSTAGE 3
#define FKT_OFF   (NSTAGE*BUF_BYTES)         // 55296
#define DSMEM_BYTES (FKT_OFF + NSTAGE*256)   // 56064

// ===================== device scratch (fp16) =====================
__device__ uint4 g_Qh4[TELEMS/8];    // Q hi (fp16, unscaled)
__device__ uint4 g_Ql4[TELEMS/8];    // Q lo residual (fp16)
__device__ uint4 g_Kh4[TELEMS/8];    // K*0.125 fp16, compacted key order
__device__ uint4 g_Vh4[TELEMS/8];    // V fp16, compacted key order
__device__ int   g_kcnt[BATCH];      // unmasked keys per batch
__device__ int   g_kidx[BATCH*SEQ];  // compacted -> original key index
__device__ float g_kidxf[BATCH*SEQ]; // same, as float (for decay)

// ===================== helpers =====================
__device__ __forceinline__ uint32_t smem_u32(const void* p) {
    uint32_t a;
    asm("{ .reg .u64 t; cvta.to.shared.u64 t, %1; cvt.u32.u64 %0, t; }" : "=r"(a) : "l"(p));
    return a;
}
__device__ __forceinline__ uint32_t pack_f16x2(float hi, float lo) {
    uint32_t r;
    asm("cvt.rn.f16x2.f32 %0, %1, %2;" : "=r"(r) : "f"(hi), "f"(lo));
    return r;
}
__device__ __forceinline__ float2 unpack_f16x2(uint32_t v) {
    float lo, hi;
    asm("{ .reg .b16 l, h; mov.b32 {l, h}, %2; cvt.f32.f16 %0, l; cvt.f32.f16 %1, h; }"
        : "=f"(lo), "=f"(hi) : "r"(v));
    return make_float2(lo, hi);
}
__device__ __forceinline__ float ex2f(float x) {
    float r;
    asm("ex2.approx.ftz.f32 %0, %1;" : "=f"(r) : "f"(x));
    return r;
}
__device__ __forceinline__ void ldm4(uint32_t r[4], uint32_t addr) {
    asm volatile("ldmatrix.sync.aligned.m8n8.x4.shared.b16 {%0,%1,%2,%3}, [%4];"
        : "=r"(r[0]), "=r"(r[1]), "=r"(r[2]), "=r"(r[3]) : "r"(addr));
}
__device__ __forceinline__ void ldm4t(uint32_t r[4], uint32_t addr) {
    asm volatile("ldmatrix.sync.aligned.m8n8.x4.trans.shared.b16 {%0,%1,%2,%3}, [%4];"
        : "=r"(r[0]), "=r"(r[1]), "=r"(r[2]), "=r"(r[3]) : "r"(addr));
}
__device__ __forceinline__ void mma16816(float c[4], const uint32_t a[4],
                                         uint32_t b0, uint32_t b1) {
    asm volatile(
        "mma.sync.aligned.m16n8k16.row.col.f32.f16.f16.f32 "
        "{%0,%1,%2,%3}, {%4,%5,%6,%7}, {%8,%9}, {%0,%1,%2,%3};"
        : "+f"(c[0]), "+f"(c[1]), "+f"(c[2]), "+f"(c[3])
        : "r"(a[0]), "r"(a[1]), "r"(a[2]), "r"(a[3]), "r"(b0), "r"(b1));
}
__device__ __forceinline__ void cpa16(uint32_t saddr, const void* gaddr) {
    asm volatile("cp.async.cg.shared.global [%0], [%1], 16;" :: "r"(saddr), "l"(gaddr));
}
#define CP_COMMIT() asm volatile("cp.async.commit_group;" ::: "memory")
#define CP_WAIT(n)  asm volatile("cp.async.wait_group %0;" :: "n"(n) : "memory")

// ===================== kernel 1: compact unmasked key indices (per batch) =====================
__global__ void mask_scan_kernel(const unsigned int* __restrict__ mask) {
    __shared__ int wsum[32];
    __shared__ int woff[32];
    const int b = blockIdx.x;
    const int t = threadIdx.x;            // 1024 threads, 2 keys each
    const int lane = t & 31, wid = t >> 5;
    const unsigned int* mb = mask + (size_t)b * SEQ;

    int j0 = 2 * t, j1 = 2 * t + 1;
    int p0 = (mb[j0] == 0u) ? 1 : 0;      // keep unmasked
    int p1 = (mb[j1] == 0u) ? 1 : 0;
    int local = p0 + p1;

    int incl = local;
    #pragma unroll
    for (int d = 1; d < 32; d <<= 1) {
        int v = __shfl_up_sync(0xffffffffu, incl, d);
        if (lane >= d) incl += v;
    }
    if (lane == 31) wsum[wid] = incl;
    __syncthreads();
    if (wid == 0) {
        int v = wsum[lane];
        int iv = v;
        #pragma unroll
        for (int d = 1; d < 32; d <<= 1) {
            int u = __shfl_up_sync(0xffffffffu, iv, d);
            if (lane >= d) iv += u;
        }
        woff[lane] = iv - v;
        if (lane == 31) g_kcnt[b] = iv;
    }
    __syncthreads();

    int base = woff[wid] + (incl - local);
    if (p0) { g_kidx[b*SEQ + base] = j0; g_kidxf[b*SEQ + base] = (float)j0; base++; }
    if (p1) { g_kidx[b*SEQ + base] = j1; g_kidxf[b*SEQ + base] = (float)j1; }

    int cnt = g_kcnt[b];
    for (int j = cnt + t; j < SEQ; j += 1024) {
        g_kidx[b*SEQ + j]  = 0;
        g_kidxf[b*SEQ + j] = 0.f;
    }
}

// ===================== kernel 2: split Q (UNscaled) into fp16 hi/lo =====================
__global__ void convert_q_kernel(const float* __restrict__ Q) {
    size_t i4 = (size_t)blockIdx.x * 256 + threadIdx.x;
    float4 q = ((const float4*)Q)[i4];
    uint32_t h0 = pack_f16x2(q.y, q.x), h1 = pack_f16x2(q.w, q.z);
    float2 u0 = unpack_f16x2(h0);
    float2 u1 = unpack_f16x2(h1);
    uint32_t l0 = pack_f16x2(q.y - u0.y, q.x - u0.x);
    uint32_t l1 = pack_f16x2(q.w - u1.y, q.z - u1.x);
    ((uint2*)g_Qh4)[i4] = make_uint2(h0, h1);
    ((uint2*)g_Ql4)[i4] = make_uint2(l0, l1);
}

// ===================== kernel 3: gather K (scaled 1/8) and V as fp16, compacted order =====================
__global__ void gather_kv_kernel(const float* __restrict__ K, const float* __restrict__ V) {
    size_t gid = (size_t)blockIdx.x * 256 + threadIdx.x;   // over TELEMS/4 = 2^21 chunks
    int chunk = (int)(gid & 15);          // 16 float4 per row (DIM=64)
    int j     = (int)((gid >> 4) & (SEQ - 1));
    int bh    = (int)(gid >> 15);
    int b     = bh >> 4;
    int cnt   = g_kcnt[b];

    uint2 kh = make_uint2(0, 0), vh = kh;
    if (j < cnt) {
        int o = g_kidx[b*SEQ + j];
        size_t src = ((size_t)bh * SEQ + o) * 16 + chunk;
        float4 k = ((const float4*)K)[src];
        kh = make_uint2(pack_f16x2(k.y * 0.125f, k.x * 0.125f),
                        pack_f16x2(k.w * 0.125f, k.z * 0.125f));
        float4 v = ((const float4*)V)[src];
        vh = make_uint2(pack_f16x2(v.y, v.x), pack_f16x2(v.w, v.z));
    }
    size_t dst = ((size_t)bh * SEQ + j) * 16 + chunk;
    ((uint2*)g_Kh4)[dst] = kh;
    ((uint2*)g_Vh4)[dst] = vh;
}

// ===================== attention kernel: fp16 2-term GEMMs, 3-stage pipeline =====================
__global__ __launch_bounds__(256, 2)
void attn_kernel(float* __restrict__ O)
{
    extern __shared__ __align__(16) char dsm[];
    const uint32_t sb = smem_u32(dsm);

    const int tid  = threadIdx.x;
    const int w    = tid >> 5;
    const int lane = tid & 31;
    const int qt = blockIdx.x, h = blockIdx.y, b = blockIdx.z;
    const int bh = b * HEADS + h;

    const int cnt   = g_kcnt[b];
    const int ntile = (cnt + 63) >> 6;
    const size_t tile_g0 = (size_t)bh * SEQ * 8;   // uint4 base of this head (8 uint4/row)

    const float L2E  = 1.4426950408889634f;
    const float C2   = 6.879347314016243e-7f;     // (2/2048^2) * log2(e)

    // per-thread load pattern for tiles (512 uint4 per array, 2 per thread)
    const int li0 = tid,       lr0 = li0 >> 3, lo0 = li0 & 7;
    const int li1 = tid + 256, lr1 = li1 >> 3, lo1 = li1 & 7;
    const uint32_t ld0 = lr0 * RS + lo0 * 16;
    const uint32_t ld1 = lr1 * RS + lo1 * 16;

    // ---- stage Q (hi/lo) into stage0/stage1 region via cp.async ----
    {
        const uint4* srcH = g_Qh4 + ((size_t)(bh * SEQ + qt * MQ) * 8);
        const uint4* srcL = g_Ql4 + ((size_t)(bh * SEQ + qt * MQ) * 8);
        #pragma unroll
        for (int i = 0; i < 4; i++) {
            int idx = tid + i * 256;          // 0..1023
            int r = idx >> 3, o = idx & 7;
            cpa16(sb + r * RS + o * 16,             srcH + idx);
            cpa16(sb + BUF_BYTES + r * RS + o * 16, srcL + idx);
        }
        CP_COMMIT();
        CP_WAIT(0);
    }
    __syncthreads();

    // ---- load Q fragments (A operands), 16 rows per warp ----
    const int qa_row  = (lane & 7) + ((lane & 8) ? 8 : 0);
    const int qa_colb = (lane & 16) ? 16 : 0;
    uint32_t qfh[4][4], qfl[4][4];
    {
        uint32_t baseH = sb + (16 * w + qa_row) * RS + qa_colb;
        uint32_t baseL = baseH + BUF_BYTES;
        #pragma unroll
        for (int ks = 0; ks < 4; ks++) {
            ldm4(qfh[ks], baseH + 32 * ks);
            ldm4(qfl[ks], baseL + 32 * ks);
        }
    }
    __syncthreads();   // stage buffers about to be overwritten by tiles 0/1

    // ---- per-thread state ----
    float oacc[8][4];
    #pragma unroll
    for (int nt = 0; nt < 8; nt++)
        #pragma unroll
        for (int e = 0; e < 4; e++) oacc[nt][e] = 0.f;
    float l0 = 0.f, l1 = 0.f;

    const int   q4   = lane >> 2;
    const int   col0 = 2 * (lane & 3);
    const int   r0g  = qt * MQ + w * 16 + q4;
    const float fi0  = (float)r0g;

    const int kb_row  = (lane & 7) + ((lane & 16) ? 8 : 0);
    const int kb_colb = (lane & 8) ? 16 : 0;
    const int vb_row  = (lane & 7) + ((lane & 8) ? 8 : 0);
    const int vb_colb = (lane & 16) ? 16 : 0;

    // issue tile T (clamped) into stage S
    #define ISSUE_TILE(T, S) do { \
        int _T = (T) < ntile ? (T) : ntile - 1; \
        const uint32_t bb_ = sb + (S) * BUF_BYTES; \
        size_t gb_ = tile_g0 + (size_t)_T * 512; \
        cpa16(bb_ + ld0,        g_Kh4 + gb_ + li0); \
        cpa16(bb_ + ld1,        g_Kh4 + gb_ + li1); \
        cpa16(bb_ + 9216 + ld0, g_Vh4 + gb_ + li0); \
        cpa16(bb_ + 9216 + ld1, g_Vh4 + gb_ + li1); \
        if (tid < 16) cpa16(sb + FKT_OFF + (S) * 256 + tid * 16, \
                            g_kidxf + b * SEQ + _T * NKV + tid * 4); \
        CP_COMMIT(); \
    } while (0)

    ISSUE_TILE(0, 0);
    ISSUE_TILE(1, 1);

    int bsel = 0, isel = 2;
    for (int t = 0; t < ntile; t++) {
        const int kt = t * NKV;
        CP_WAIT(1);        // tile t's group complete
        __syncthreads();   // visibility of tile t + all warps done reading tile t-1's buffer
        ISSUE_TILE(t + 2, isel);

        const uint32_t sKH = sb + bsel * BUF_BYTES;
        const uint32_t sVH = sKH + 9216;
        const float* fktp = (const float*)(dsm + FKT_OFF + bsel * 256);

        // ---- S = Q K^T (fp16 2-term: QhKh + QlKh) ----
        float c[8][4];
        #pragma unroll
        for (int nt = 0; nt < 8; nt++)
            #pragma unroll
            for (int e = 0; e < 4; e++) c[nt][e] = 0.f;

        #pragma unroll
        for (int ks = 0; ks < 4; ks++) {
            uint32_t bb[8][2];
            #pragma unroll
            for (int g = 0; g < 4; g++) {
                uint32_t r4[4];
                ldm4(r4, sKH + (16 * g + kb_row) * RS + 32 * ks + kb_colb);
                bb[2*g][0] = r4[0]; bb[2*g][1] = r4[1];
                bb[2*g+1][0] = r4[2]; bb[2*g+1][1] = r4[3];
            }
            #pragma unroll
            for (int nt = 0; nt < 8; nt++) mma16816(c[nt], qfh[ks], bb[nt][0], bb[nt][1]);
            #pragma unroll
            for (int nt = 0; nt < 8; nt++) mma16816(c[nt], qfl[ks], bb[nt][0], bb[nt][1]);
        }

        // ---- tail masking: only the last tile has partial keys ----
        if (t == ntile - 1) {
            const int lim = cnt - kt;
            #pragma unroll
            for (int nt = 0; nt < 8; nt++) {
                int j0i = 8 * nt + col0;
                if (j0i >= lim)     { c[nt][0] = -1e30f; c[nt][2] = -1e30f; }
                if (j0i + 1 >= lim) { c[nt][1] = -1e30f; c[nt][3] = -1e30f; }
            }
        }

        // ---- interleaved: per k-step produce P fragments (fp16 hi/lo) then PV MMAs ----
        float lsA0 = 0.f, lsB0 = 0.f, lsA1 = 0.f, lsB1 = 0.f;
        #pragma unroll
        for (int ksv = 0; ksv < 4; ksv++) {
            uint32_t ah[4], al[4];
            #pragma unroll
            for (int half = 0; half < 2; half++) {
                const int nt = 2 * ksv + half;
                float2 fk2 = *(const float2*)&fktp[8 * nt + col0];
                float rA0 = fi0 - fk2.x, rA1 = fi0 - fk2.y;
                float rB0 = rA0 + 8.f,   rB1 = rA1 + 8.f;
                float t00 = c[nt][0] * L2E;
                float t01 = c[nt][1] * L2E;
                float t10 = c[nt][2] * L2E;
                float t11 = c[nt][3] * L2E;
                float p00 = ex2f(t00);
                float p01 = ex2f(t01);
                float p10 = ex2f(t10);
                float p11 = ex2f(t11);
                lsA0 += p00; lsB0 += p01;
                lsA1 += p10; lsB1 += p11;
                float pd00 = ex2f(fmaf(-C2 * rA0, rA0, t00));
                float pd01 = ex2f(fmaf(-C2 * rA1, rA1, t01));
                float pd10 = ex2f(fmaf(-C2 * rB0, rB0, t10));
                float pd11 = ex2f(fmaf(-C2 * rB1, rB1, t11));
                uint32_t h0 = pack_f16x2(pd01, pd00);
                uint32_t h1 = pack_f16x2(pd11, pd10);
                float2 u0 = unpack_f16x2(h0);
                float2 u1 = unpack_f16x2(h1);
                ah[2*half]     = h0;
                ah[2*half + 1] = h1;
                al[2*half]     = pack_f16x2(pd01 - u0.y, pd00 - u0.x);
                al[2*half + 1] = pack_f16x2(pd11 - u1.y, pd10 - u1.x);
            }
            uint32_t bb[8][2];
            #pragma unroll
            for (int g = 0; g < 4; g++) {
                uint32_t r4[4];
                ldm4t(r4, sVH + (16 * ksv + vb_row) * RS + 32 * g + vb_colb);
                bb[2*g][0] = r4[0]; bb[2*g][1] = r4[1];
                bb[2*g+1][0] = r4[2]; bb[2*g+1][1] = r4[3];
            }
            #pragma unroll
            for (int nt = 0; nt < 8; nt++) mma16816(oacc[nt], ah, bb[nt][0], bb[nt][1]);
            #pragma unroll
            for (int nt = 0; nt < 8; nt++) mma16816(oacc[nt], al, bb[nt][0], bb[nt][1]);
        }
        l0 += lsA0 + lsB0;
        l1 += lsA1 + lsB1;

        bsel = (bsel == NSTAGE - 1) ? 0 : bsel + 1;
        isel = (isel == NSTAGE - 1) ? 0 : isel + 1;
    }

    // ---- reduce denominator across the quad ----
    l0 += __shfl_xor_sync(0xffffffffu, l0, 1);
    l0 += __shfl_xor_sync(0xffffffffu, l0, 2);
    l1 += __shfl_xor_sync(0xffffffffu, l1, 1);
    l1 += __shfl_xor_sync(0xffffffffu, l1, 2);

    // ---- write out ----
    float inv0 = (l0 > 0.f) ? (1.f / l0) : 0.f;
    float inv1 = (l1 > 0.f) ? (1.f / l1) : 0.f;
    float* o0 = O + ((size_t)bh * SEQ + r0g) * DIM;
    float* o1 = o0 + 8 * DIM;
    #pragma unroll
    for (int nt = 0; nt < 8; nt++) {
        int j = 8 * nt + col0;
        *(float2*)(o0 + j) = make_float2(oacc[nt][0] * inv0, oacc[nt][1] * inv0);
        *(float2*)(o1 + j) = make_float2(oacc[nt][2] * inv1, oacc[nt][3] * inv1);
    }
}

// ===================== host launch =====================
extern "C" void kernel_launch(void* const* d_in, const int* in_sizes, int n_in,
                              void* d_out, int out_size)
{
    const float* Q = (const float*)d_in[0];
    const float* K = (const float*)d_in[1];
    const float* V = (const float*)d_in[2];
    const unsigned int* mask = (const unsigned int*)d_in[3];
    float* O = (float*)d_out;

    static int configured = 0;
    if (!configured) {
        cudaFuncSetAttribute(attn_kernel, cudaFuncAttributeMaxDynamicSharedMemorySize,
                             DSMEM_BYTES);
        configured = 1;
    }

    mask_scan_kernel<<<BATCH, 1024>>>(mask);
    convert_q_kernel<<<TELEMS / 4 / 256, 256>>>(Q);
    gather_kv_kernel<<<TELEMS / 4 / 256, 256>>>(K, V);
    attn_kernel<<<dim3(SEQ / MQ, HEADS, BATCH), 256, DSMEM_BYTES>>>(O);
}